// round 12
// baseline (speedup 1.0000x reference)
#include <cuda_runtime.h>
#include <cuda_bf16.h>
#include <cstdint>

// Problem constants
#define L_DIM 4096
#define N_DIM 8
#define C_DIM 512
#define OUT_DIM 512
#define G_DIM 8
#define KS_DIM 64
#define W_DIM 64          // L / KS
#define B_DIM 512         // N * W

// Scratch: qkv intermediate [B][1024][64] (BN already applied)
__device__ float g_qkv[(size_t)B_DIM * 1024 * 64];
// Split bf16 copies (X relaid to [b*64+h][c], W as [o][c])
__device__ __nv_bfloat16 g_xhi[(size_t)32768 * 512];
__device__ __nv_bfloat16 g_xlo[(size_t)32768 * 512];
__device__ __nv_bfloat16 g_whi[(size_t)1024 * 512];
__device__ __nv_bfloat16 g_wlo[(size_t)1024 * 512];
// Padded relative table: row stride 128 (float4-aligned rows)
__device__ float g_relp[128 * 128];

// ===========================================================================
// helpers
// ===========================================================================
__device__ __forceinline__ uint32_t smem_u32(const void* p) {
    uint32_t a;
    asm("{ .reg .u64 t; cvta.to.shared.u64 t, %1; cvt.u32.u64 %0, t; }"
        : "=r"(a) : "l"(p));
    return a;
}

__device__ __forceinline__ void cp16(uint32_t dst, const void* src) {
    asm volatile("cp.async.ca.shared.global [%0], [%1], 16;"
                 :: "r"(dst), "l"(src) : "memory");
}

// hi = truncate-to-bf16(x) (bitwise), lo = rn_bf16(x - hi).
__device__ __forceinline__ void split_store4(
    float4 a, __nv_bfloat16* hi, __nv_bfloat16* lo, size_t off)
{
    uint32_t x = __float_as_uint(a.x), y = __float_as_uint(a.y);
    uint32_t z = __float_as_uint(a.z), w = __float_as_uint(a.w);
    uint32_t h01 = __byte_perm(x, y, 0x7632);
    uint32_t h23 = __byte_perm(z, w, 0x7632);
    float lx = a.x - __uint_as_float(x & 0xFFFF0000u);
    float ly = a.y - __uint_as_float(y & 0xFFFF0000u);
    float lz = a.z - __uint_as_float(z & 0xFFFF0000u);
    float lw = a.w - __uint_as_float(w & 0xFFFF0000u);
    uint32_t l01, l23;
    asm("cvt.rn.bf16x2.f32 %0, %1, %2;" : "=r"(l01) : "f"(ly), "f"(lx));
    asm("cvt.rn.bf16x2.f32 %0, %1, %2;" : "=r"(l23) : "f"(lw), "f"(lz));
    *(uint2*)(hi + off) = make_uint2(h01, h23);
    *(uint2*)(lo + off) = make_uint2(l01, l23);
}

__device__ __forceinline__ void mma_bf16(
    float d[4], uint32_t a0, uint32_t a1, uint32_t a2, uint32_t a3,
    uint32_t b0, uint32_t b1)
{
    asm volatile(
        "mma.sync.aligned.m16n8k16.row.col.f32.bf16.bf16.f32 "
        "{%0,%1,%2,%3}, {%4,%5,%6,%7}, {%8,%9}, {%0,%1,%2,%3};"
        : "+f"(d[0]), "+f"(d[1]), "+f"(d[2]), "+f"(d[3])
        : "r"(a0), "r"(a1), "r"(a2), "r"(a3), "r"(b0), "r"(b1));
}

// ===========================================================================
// Kernel 0: split X and W into bf16 hi/lo global scratch; also pad rel.
// ===========================================================================
__global__ __launch_bounds__(256) void split_prep(
    const float* __restrict__ x, const float* __restrict__ w,
    const float* __restrict__ rel)
{
    int idx = blockIdx.x * 256 + threadIdx.x;   // one float4 each
    int row = idx >> 7;
    int q   = idx & 127;
    if (row < 32768) {
        int b = row >> 6, h = row & 63;
        int n = b >> 6,  wi = b & 63;
        float4 a = *(const float4*)(x + (size_t)(wi * 64 + h) * 4096
                                      + n * 512 + q * 4);
        split_store4(a, g_xhi, g_xlo, (size_t)row * 512 + q * 4);
    } else if (row < 33792) {
        int o = row - 32768;
        float4 a = *(const float4*)(w + (size_t)o * 512 + q * 4);
        split_store4(a, g_whi, g_wlo, (size_t)o * 512 + q * 4);
    }
    // rel pad handled by dedicated tail blocks:
    int tidg = blockIdx.x * 256 + threadIdx.x - 33792 * 128;
    if (tidg >= 0 && tidg < 128 * 128) {
        int r = tidg >> 7, d = tidg & 127;
        g_relp[tidg] = (d < 127) ? rel[r * 127 + d] : 0.f;
    }
}

// ===========================================================================
// Kernel 1: QKV GEMM via mma.sync bf16 split-precision, cp.async pipelined.
//  Tile 128(o) x 128(n = 2 windows x 64 h); grid = (8 ot, 256 bp), 256 thr,
//  2 CTAs/SM (80 KB smem each): sibling CTA hides barrier/pipeline bubbles.
//  K = 512 in 16 chunks of 32, 2-stage double buffer. GPAD=40 (proven).
// ===========================================================================
#define GPAD 40   // bf16 row stride
#define KC 32
#define NCHUNK 16

// smem offsets in bf16 units: [Whi|Wlo|Xhi|Xlo] x 2 stages, 128 rows each
#define SW_OFF(s, hl) (((s) * 2 + (hl)) * 128 * GPAD)
#define SX_OFF(s, hl) (4 * 128 * GPAD + ((s) * 2 + (hl)) * 128 * GPAD)
#define GEMM_SMEM_BF16 (8 * 128 * GPAD)
#define GEMM_SMEM_BYTES (GEMM_SMEM_BF16 * 2)     // 81920 bytes

__global__ __launch_bounds__(256, 2) void qkv_gemm_mma(
    const float* __restrict__ gg, const float* __restrict__ gb,
    const float* __restrict__ gm, const float* __restrict__ gv)
{
    extern __shared__ __nv_bfloat16 smem[];
    const uint32_t sb = smem_u32(smem);

    const int tid  = threadIdx.x;
    const int lane = tid & 31;
    const int wid  = tid >> 5;
    const int wm   = wid >> 2;          // 0..1
    const int wn   = wid & 3;           // 0..3
    const int o0   = wm * 64;
    const int n0   = wn * 32;
    const int gid  = lane >> 2;         // 0..7
    const int tig  = lane & 3;          // 0..3
    const int ot   = blockIdx.x;
    const int bp   = blockIdx.y;        // 2-window group

    const __nv_bfloat16* whiB = g_whi + (size_t)(ot * 128) * 512;
    const __nv_bfloat16* wloB = g_wlo + (size_t)(ot * 128) * 512;
    const __nv_bfloat16* xhiB = g_xhi + (size_t)(bp * 128) * 512;
    const __nv_bfloat16* xloB = g_xlo + (size_t)(bp * 128) * 512;

    float acc[4][4][4];
#pragma unroll
    for (int m = 0; m < 4; m++)
#pragma unroll
        for (int n = 0; n < 4; n++)
#pragma unroll
            for (int r = 0; r < 4; r++) acc[m][n][r] = 0.f;

    auto load_chunk = [&](int c, int s) {
        const int ct = c * KC;
        // W tile 128x32 and X tile 128x32: each 512 quad-slots
#pragma unroll
        for (int t = 0; t < 2; t++) {
            int slot = tid + t * 256;        // 0..511
            int row = slot >> 2, q = slot & 3;
            size_t g = (size_t)row * 512 + ct + q * 8;
            uint32_t d = row * GPAD + q * 8;
            cp16(sb + (SW_OFF(s, 0) + d) * 2, whiB + g);
            cp16(sb + (SW_OFF(s, 1) + d) * 2, wloB + g);
            cp16(sb + (SX_OFF(s, 0) + d) * 2, xhiB + g);
            cp16(sb + (SX_OFF(s, 1) + d) * 2, xloB + g);
        }
        asm volatile("cp.async.commit_group;" ::: "memory");
    };

    load_chunk(0, 0);
    load_chunk(1, 1);

    for (int c = 0; c < NCHUNK; c++) {
        const int s = c & 1;
        if (c < NCHUNK - 1) asm volatile("cp.async.wait_group 1;" ::: "memory");
        else                asm volatile("cp.async.wait_group 0;" ::: "memory");
        __syncthreads();

        const __nv_bfloat16* Whi = smem + SW_OFF(s, 0);
        const __nv_bfloat16* Wlo = smem + SW_OFF(s, 1);
        const __nv_bfloat16* Xhi = smem + SX_OFF(s, 0);
        const __nv_bfloat16* Xlo = smem + SX_OFF(s, 1);

#pragma unroll
        for (int ks = 0; ks < 2; ks++) {
            const int kb = ks * 16 + tig * 2;
            // ---- load B fragments (4 n-tiles, hi+lo) ----
            uint32_t Bh[4][2], Bl[4][2];
#pragma unroll
            for (int n = 0; n < 4; n++) {
                int r = (n0 + n * 8 + gid) * GPAD + kb;
                Bh[n][0] = *(const uint32_t*)&Xhi[r];
                Bh[n][1] = *(const uint32_t*)&Xhi[r + 8];
                Bl[n][0] = *(const uint32_t*)&Xlo[r];
                Bl[n][1] = *(const uint32_t*)&Xlo[r + 8];
            }
            // ---- load A fragments for ALL 4 m-tiles (hi+lo) ----
            uint32_t Ah[4][4], Al[4][4];
#pragma unroll
            for (int m = 0; m < 4; m++) {
                int r0 = (o0 + m * 16 + gid) * GPAD + kb;
                int r1 = r0 + 8 * GPAD;
                Ah[m][0] = *(const uint32_t*)&Whi[r0];
                Ah[m][1] = *(const uint32_t*)&Whi[r1];
                Ah[m][2] = *(const uint32_t*)&Whi[r0 + 8];
                Ah[m][3] = *(const uint32_t*)&Whi[r1 + 8];
                Al[m][0] = *(const uint32_t*)&Wlo[r0];
                Al[m][1] = *(const uint32_t*)&Wlo[r1];
                Al[m][2] = *(const uint32_t*)&Wlo[r0 + 8];
                Al[m][3] = *(const uint32_t*)&Wlo[r1 + 8];
            }
            // ---- product-type outer (same-acc HMMAs spaced) ----
#pragma unroll
            for (int m = 0; m < 4; m++)
#pragma unroll
                for (int n = 0; n < 4; n++)
                    mma_bf16(acc[m][n],
                             Ah[m][0], Ah[m][1], Ah[m][2], Ah[m][3],
                             Bh[n][0], Bh[n][1]);
#pragma unroll
            for (int m = 0; m < 4; m++)
#pragma unroll
                for (int n = 0; n < 4; n++)
                    mma_bf16(acc[m][n],
                             Ah[m][0], Ah[m][1], Ah[m][2], Ah[m][3],
                             Bl[n][0], Bl[n][1]);
#pragma unroll
            for (int m = 0; m < 4; m++)
#pragma unroll
                for (int n = 0; n < 4; n++)
                    mma_bf16(acc[m][n],
                             Al[m][0], Al[m][1], Al[m][2], Al[m][3],
                             Bh[n][0], Bh[n][1]);
        }

        if (c + 2 < NCHUNK) {
            __syncthreads();
            load_chunk(c + 2, s);
        }
    }

    // ---- epilogue: BN affine + store to g_qkv ----
#pragma unroll
    for (int m = 0; m < 4; m++) {
#pragma unroll
        for (int rr = 0; rr < 2; rr++) {
            int o = ot * 128 + o0 + m * 16 + gid + rr * 8;
            float sc = gg[o] * rsqrtf(gv[o] + 1e-5f);
            float sh = gb[o] - gm[o] * sc;
#pragma unroll
            for (int n = 0; n < 4; n++) {
                int col = n0 + n * 8 + 2 * tig;
                int b = bp * 2 + (col >> 6);
                int h = col & 63;
                float2 v;
                v.x = acc[m][n][rr * 2 + 0] * sc + sh;
                v.y = acc[m][n][rr * 2 + 1] * sc + sh;
                *(float2*)(g_qkv + (size_t)b * 65536 + (size_t)o * 64 + h) = v;
            }
        }
    }
}

// ---------------------------------------------------------------------------
// Kernel 2: attention per (b, g).  grid = (8 g, 512 b), 256 threads.
// smem: q/k (64x68, overlaid by pre-softmax sim), v (64x68), rel (128x128).
// Softmax output written TRANSPOSED into dead rel rows 0..63 (sT) so the
// sv/sve loop reads are bank-conflict-free.  (R9 config, banked)
// ---------------------------------------------------------------------------
#define SM_V (64 * 68)
#define SM_R (128 * 68)
#define ATTN_SMEM_FLOATS (128 * 68 + 128 * 128)
#define ATTN_SMEM_BYTES (ATTN_SMEM_FLOATS * 4)

__global__ __launch_bounds__(256, 2) void attn_kernel(
    const float* __restrict__ simg, const float* __restrict__ simb,
    const float* __restrict__ simm, const float* __restrict__ simv,
    const float* __restrict__ outg, const float* __restrict__ outb,
    const float* __restrict__ outm, const float* __restrict__ outv,
    float* __restrict__ out)
{
    extern __shared__ float sm[];
    float* sQ = sm;                 // rows 0..31
    float* sK = sm + 32 * 68;       // rows 32..63
    float* sS = sm;                 // OVERLAY (pre-softmax sim) after sync
    float* sV = sm + SM_V;
    float* sR = sm + SM_R;
    float* sT = sm + SM_R;          // OVERLAY: transposed softmax output in
                                    // dead rel rows 0..63 (stride 68)
    const uint32_t sb = smem_u32(sm);

    const int g   = blockIdx.x;
    const int b   = blockIdx.y;
    const int n   = b >> 6;
    const int wi  = b & 63;
    const int tid = threadIdx.x;
    const int tx  = tid & 15;
    const int ty  = tid >> 4;

    // Load rel table (padded, contiguous) via cp.async
#pragma unroll
    for (int t = 0; t < 16; t++) {
        int idx = (tid + t * 256) * 4;     // 0..16380
        cp16(sb + (SM_R + idx) * 4, g_relp + idx);
    }
    // Load q/k/v tiles from the qkv scratch via cp.async
    const float* base = g_qkv + (size_t)b * 65536 + (size_t)g * 128 * 64;
#pragma unroll
    for (int t = 0; t < 8; t++) {
        int idx = (tid + t * 256) * 4;     // element index, 0..8188
        int cc = idx >> 6;
        int h  = idx & 63;
        uint32_t dst = (cc < 64) ? (cc * 68 + h)
                                 : (SM_V + (cc - 64) * 68 + h);
        cp16(sb + dst * 4, base + idx);
    }
    asm volatile("cp.async.commit_group;" ::: "memory");
    asm volatile("cp.async.wait_group 0;" ::: "memory");
    __syncthreads();

    // --------------- sim = BN(qk) + BN(qr) + BN(kr) ---------------
    const int i0 = ty * 4;
    const int j0 = tx * 4;
    const int dq0 = i0 - j0 + 60;
    const int dk0 = j0 - i0 + 60;

    float aqk[4][4], aqr[4][4], akr[4][4];
#pragma unroll
    for (int a = 0; a < 4; a++)
#pragma unroll
        for (int c = 0; c < 4; c++) { aqk[a][c] = 0.f; aqr[a][c] = 0.f; akr[a][c] = 0.f; }

#pragma unroll 4
    for (int c = 0; c < 32; c++) {
        float4 qv4 = *(const float4*)&sQ[c * 68 + i0];
        float4 kv4 = *(const float4*)&sK[c * 68 + j0];
        float4 rq0 = *(const float4*)&sR[c * 128 + dq0];
        float4 rq1 = *(const float4*)&sR[c * 128 + dq0 + 4];
        float4 rk0 = *(const float4*)&sR[(32 + c) * 128 + dk0];
        float4 rk1 = *(const float4*)&sR[(32 + c) * 128 + dk0 + 4];
        float qv[4] = {qv4.x, qv4.y, qv4.z, qv4.w};
        float kv[4] = {kv4.x, kv4.y, kv4.z, kv4.w};
        float rq[8] = {rq0.x, rq0.y, rq0.z, rq0.w, rq1.x, rq1.y, rq1.z, rq1.w};
        float rk[8] = {rk0.x, rk0.y, rk0.z, rk0.w, rk1.x, rk1.y, rk1.z, rk1.w};
#pragma unroll
        for (int ii = 0; ii < 4; ii++)
#pragma unroll
            for (int jj = 0; jj < 4; jj++) {
                aqk[ii][jj] = fmaf(qv[ii], kv[jj], aqk[ii][jj]);
                aqr[ii][jj] = fmaf(qv[ii], rq[ii - jj + 3], aqr[ii][jj]);
                akr[ii][jj] = fmaf(kv[jj], rk[jj - ii + 3], akr[ii][jj]);
            }
    }

    const float s_qk = simg[g]      * rsqrtf(simv[g]      + 1e-5f);
    const float s_qr = simg[8 + g]  * rsqrtf(simv[8 + g]  + 1e-5f);
    const float s_kr = simg[16 + g] * rsqrtf(simv[16 + g] + 1e-5f);
    const float sh_sum = (simb[g]      - simm[g]      * s_qk)
                       + (simb[8 + g]  - simm[8 + g]  * s_qr)
                       + (simb[16 + g] - simm[16 + g] * s_kr);

    __syncthreads();   // all reads of q/k (and rel rows 0..63) done
#pragma unroll
    for (int ii = 0; ii < 4; ii++)
#pragma unroll
        for (int jj = 0; jj < 4; jj++)
            sS[(i0 + ii) * 68 + j0 + jj] =
                s_qk * aqk[ii][jj] + s_qr * aqr[ii][jj] + s_kr * akr[ii][jj] + sh_sum;
    __syncthreads();

    // ---- softmax over j; output written transposed into sT[j][i] ----
    {
        int warp = tid >> 5, lane = tid & 31;
#pragma unroll
        for (int r = 0; r < 8; r++) {
            int i = warp * 8 + r;
            float a0 = sS[i * 68 + lane];
            float a1 = sS[i * 68 + lane + 32];
            float mx = fmaxf(a0, a1);
#pragma unroll
            for (int off = 16; off > 0; off >>= 1)
                mx = fmaxf(mx, __shfl_xor_sync(0xffffffffu, mx, off));
            float e0 = __expf(a0 - mx);
            float e1 = __expf(a1 - mx);
            float s = e0 + e1;
#pragma unroll
            for (int off = 16; off > 0; off >>= 1)
                s += __shfl_xor_sync(0xffffffffu, s, off);
            float inv = 1.0f / s;
            sT[lane * 68 + i]        = e0 * inv;   // sim[i][lane]
            sT[(lane + 32) * 68 + i] = e1 * inv;   // sim[i][lane+32]
        }
    }
    __syncthreads();

    // --------------- sv / sve (transposed sim reads, conflict-free) -------
    const int c0  = ty * 4;
    const int ii0 = tx * 4;
    float asv[4][4], asve[4][4];
#pragma unroll
    for (int a = 0; a < 4; a++)
#pragma unroll
        for (int c = 0; c < 4; c++) { asv[a][c] = 0.f; asve[a][c] = 0.f; }

    // carry: rcar[cc] holds rel[(64+c0+cc)*128 + ii0 - 4*jq + 64 .. +67]
    float4 rcar[4];
#pragma unroll
    for (int cc = 0; cc < 4; cc++)
        rcar[cc] = *(const float4*)&sR[(64 + c0 + cc) * 128 + ii0 + 64];

#pragma unroll 2
    for (int jq = 0; jq < 16; jq++) {
        // sjf[jj][t] = sim[ii0+t][4*jq+jj]  (float4 over i from sT)
        float sjf[4][4];
#pragma unroll
        for (int jj = 0; jj < 4; jj++) {
            float4 v = *(const float4*)&sT[(jq * 4 + jj) * 68 + ii0];
            sjf[jj][0] = v.x; sjf[jj][1] = v.y; sjf[jj][2] = v.z; sjf[jj][3] = v.w;
        }
        float4 vv[4];
#pragma unroll
        for (int t = 0; t < 4; t++) vv[t] = *(const float4*)&sV[(c0 + t) * 68 + jq * 4];

#pragma unroll
        for (int cc = 0; cc < 4; cc++) {
            float4 r0 = *(const float4*)&sR[(64 + c0 + cc) * 128 + ii0 - jq * 4 + 60];
            float rv8[8] = {r0.x, r0.y, r0.z, r0.w,
                            rcar[cc].x, rcar[cc].y, rcar[cc].z, rcar[cc].w};
#pragma unroll
            for (int t = 0; t < 4; t++) {
                float a = asv[cc][t];
                a = fmaf(sjf[0][t], vv[cc].x, a);
                a = fmaf(sjf[1][t], vv[cc].y, a);
                a = fmaf(sjf[2][t], vv[cc].z, a);
                a = fmaf(sjf[3][t], vv[cc].w, a);
                asv[cc][t] = a;
                float e = asve[cc][t];
                e = fmaf(sjf[0][t], rv8[t + 3], e);
                e = fmaf(sjf[1][t], rv8[t + 2], e);
                e = fmaf(sjf[2][t], rv8[t + 1], e);
                e = fmaf(sjf[3][t], rv8[t + 0], e);
                asve[cc][t] = e;
            }
            rcar[cc] = r0;
        }
    }

    // --------------- out BN + interleaved sum, transpose via smem ---------------
    float res[4][4];
#pragma unroll
    for (int cc = 0; cc < 4; cc++) {
        int c  = c0 + cc;
        int o0 = g * 128 + 2 * c;
        float sc0 = outg[o0]     * rsqrtf(outv[o0]     + 1e-5f);
        float sh0 = outb[o0]     - outm[o0]     * sc0;
        float sc1 = outg[o0 + 1] * rsqrtf(outv[o0 + 1] + 1e-5f);
        float sh1 = outb[o0 + 1] - outm[o0 + 1] * sc1;
#pragma unroll
        for (int t = 0; t < 4; t++)
            res[cc][t] = sc0 * asv[cc][t] + sc1 * asve[cc][t] + sh0 + sh1;
    }
    __syncthreads();
#pragma unroll
    for (int cc = 0; cc < 4; cc++)
#pragma unroll
        for (int t = 0; t < 4; t++)
            sS[(c0 + cc) * 68 + ii0 + t] = res[cc][t];
    __syncthreads();

    // coalesced write: out[(wi*64+i)*4096 + n*512 + g*64 + c]
    float* ob = out + (size_t)(wi * 64) * 4096 + n * 512 + g * 64;
    {
        int c = tid & 63;
        int ib = tid >> 6;     // 0..3
#pragma unroll
        for (int r = 0; r < 16; r++) {
            int i = ib + r * 4;
            ob[(size_t)i * 4096 + c] = sS[c * 68 + i];
        }
    }
}

// ---------------------------------------------------------------------------
extern "C" void kernel_launch(void* const* d_in, const int* in_sizes, int n_in,
                              void* d_out, int out_size)
{
    const float* x     = (const float*)d_in[0];
    const float* qkv_w = (const float*)d_in[1];
    const float* rel   = (const float*)d_in[2];
    const float* qkv_g = (const float*)d_in[3];
    const float* qkv_b = (const float*)d_in[4];
    const float* qkv_m = (const float*)d_in[5];
    const float* qkv_v = (const float*)d_in[6];
    const float* sim_g = (const float*)d_in[7];
    const float* sim_b = (const float*)d_in[8];
    const float* sim_m = (const float*)d_in[9];
    const float* sim_v = (const float*)d_in[10];
    const float* out_g = (const float*)d_in[11];
    const float* out_b = (const float*)d_in[12];
    const float* out_m = (const float*)d_in[13];
    const float* out_v = (const float*)d_in[14];
    float* out = (float*)d_out;

    // 33792*128 float4 slots for X/W split + 16384 threads for rel pad
    int total_threads = 33792 * 128 + 128 * 128;
    split_prep<<<(total_threads + 255) / 256, 256>>>(x, qkv_w, rel);

    cudaFuncSetAttribute(qkv_gemm_mma,
                         cudaFuncAttributeMaxDynamicSharedMemorySize,
                         GEMM_SMEM_BYTES);
    qkv_gemm_mma<<<dim3(8, 256), 256, GEMM_SMEM_BYTES>>>(
        qkv_g, qkv_b, qkv_m, qkv_v);

    cudaFuncSetAttribute(attn_kernel,
                         cudaFuncAttributeMaxDynamicSharedMemorySize,
                         ATTN_SMEM_BYTES);
    attn_kernel<<<dim3(8, 512), 256, ATTN_SMEM_BYTES>>>(
        sim_g, sim_b, sim_m, sim_v,
        out_g, out_b, out_m, out_v, out);
}

// round 13
// speedup vs baseline: 1.0331x; 1.0331x over previous
#include <cuda_runtime.h>
#include <cuda_bf16.h>
#include <cstdint>

// Problem constants
#define L_DIM 4096
#define N_DIM 8
#define C_DIM 512
#define OUT_DIM 512
#define G_DIM 8
#define KS_DIM 64
#define W_DIM 64          // L / KS
#define B_DIM 512         // N * W

// Scratch: qkv intermediate [B][1024][64] (BN already applied)
__device__ float g_qkv[(size_t)B_DIM * 1024 * 64];
// Split bf16 copies (X relaid to [b*64+h][c], W as [o][c])
__device__ __nv_bfloat16 g_xhi[(size_t)32768 * 512];
__device__ __nv_bfloat16 g_xlo[(size_t)32768 * 512];
__device__ __nv_bfloat16 g_whi[(size_t)1024 * 512];
__device__ __nv_bfloat16 g_wlo[(size_t)1024 * 512];
// Padded relative table: row stride 128 (float4-aligned rows)
__device__ float g_relp[128 * 128];

// ===========================================================================
// helpers
// ===========================================================================
__device__ __forceinline__ uint32_t smem_u32(const void* p) {
    uint32_t a;
    asm("{ .reg .u64 t; cvta.to.shared.u64 t, %1; cvt.u32.u64 %0, t; }"
        : "=r"(a) : "l"(p));
    return a;
}

__device__ __forceinline__ void cp16(uint32_t dst, const void* src) {
    asm volatile("cp.async.ca.shared.global [%0], [%1], 16;"
                 :: "r"(dst), "l"(src) : "memory");
}

// hi = truncate-to-bf16(x) (bitwise), lo = rn_bf16(x - hi).
__device__ __forceinline__ void split_store4(
    float4 a, __nv_bfloat16* hi, __nv_bfloat16* lo, size_t off)
{
    uint32_t x = __float_as_uint(a.x), y = __float_as_uint(a.y);
    uint32_t z = __float_as_uint(a.z), w = __float_as_uint(a.w);
    uint32_t h01 = __byte_perm(x, y, 0x7632);
    uint32_t h23 = __byte_perm(z, w, 0x7632);
    float lx = a.x - __uint_as_float(x & 0xFFFF0000u);
    float ly = a.y - __uint_as_float(y & 0xFFFF0000u);
    float lz = a.z - __uint_as_float(z & 0xFFFF0000u);
    float lw = a.w - __uint_as_float(w & 0xFFFF0000u);
    uint32_t l01, l23;
    asm("cvt.rn.bf16x2.f32 %0, %1, %2;" : "=r"(l01) : "f"(ly), "f"(lx));
    asm("cvt.rn.bf16x2.f32 %0, %1, %2;" : "=r"(l23) : "f"(lw), "f"(lz));
    *(uint2*)(hi + off) = make_uint2(h01, h23);
    *(uint2*)(lo + off) = make_uint2(l01, l23);
}

__device__ __forceinline__ void mma_bf16(
    float d[4], uint32_t a0, uint32_t a1, uint32_t a2, uint32_t a3,
    uint32_t b0, uint32_t b1)
{
    asm volatile(
        "mma.sync.aligned.m16n8k16.row.col.f32.bf16.bf16.f32 "
        "{%0,%1,%2,%3}, {%4,%5,%6,%7}, {%8,%9}, {%0,%1,%2,%3};"
        : "+f"(d[0]), "+f"(d[1]), "+f"(d[2]), "+f"(d[3])
        : "r"(a0), "r"(a1), "r"(a2), "r"(a3), "r"(b0), "r"(b1));
}

// ===========================================================================
// Kernel 0: split X and W into bf16 hi/lo global scratch; also pad rel.
// ===========================================================================
__global__ __launch_bounds__(256) void split_prep(
    const float* __restrict__ x, const float* __restrict__ w,
    const float* __restrict__ rel)
{
    int idx = blockIdx.x * 256 + threadIdx.x;   // one float4 each
    int row = idx >> 7;
    int q   = idx & 127;
    if (row < 32768) {
        int b = row >> 6, h = row & 63;
        int n = b >> 6,  wi = b & 63;
        float4 a = *(const float4*)(x + (size_t)(wi * 64 + h) * 4096
                                      + n * 512 + q * 4);
        split_store4(a, g_xhi, g_xlo, (size_t)row * 512 + q * 4);
    } else if (row < 33792) {
        int o = row - 32768;
        float4 a = *(const float4*)(w + (size_t)o * 512 + q * 4);
        split_store4(a, g_whi, g_wlo, (size_t)o * 512 + q * 4);
    }
    // rel pad handled by dedicated tail blocks:
    int tidg = blockIdx.x * 256 + threadIdx.x - 33792 * 128;
    if (tidg >= 0 && tidg < 128 * 128) {
        int r = tidg >> 7, d = tidg & 127;
        g_relp[tidg] = (d < 127) ? rel[r * 127 + d] : 0.f;
    }
}

// ===========================================================================
// Kernel 1: QKV GEMM (exact R10 config, 282us measured).
//  D[o(128), n(256 = 4 windows x 64 h)] ; grid = (8 ot, 128 bq), 256 thr.
//  K = 512 in 16 chunks of 32, 2-stage double buffer, GPAD=40.
// ===========================================================================
#define GPAD 40   // bf16 row stride
#define KC 32
#define NCHUNK 16

// smem offsets in bf16 units
#define SW_OFF(s, hl) (((s) * 2 + (hl)) * 128 * GPAD)
#define SX_OFF(s, hl) (4 * 128 * GPAD + ((s) * 2 + (hl)) * 256 * GPAD)
#define GEMM_SMEM_BF16 (4 * 128 * GPAD + 4 * 256 * GPAD)
#define GEMM_SMEM_BYTES (GEMM_SMEM_BF16 * 2)

__global__ __launch_bounds__(256, 1) void qkv_gemm_mma(
    const float* __restrict__ gg, const float* __restrict__ gb,
    const float* __restrict__ gm, const float* __restrict__ gv)
{
    extern __shared__ __nv_bfloat16 smem[];
    const uint32_t sb = smem_u32(smem);

    const int tid  = threadIdx.x;
    const int lane = tid & 31;
    const int wid  = tid >> 5;
    const int wm   = wid >> 2;          // 0..1
    const int wn   = wid & 3;           // 0..3
    const int o0   = wm * 64;
    const int n0   = wn * 64;
    const int gid  = lane >> 2;         // 0..7
    const int tig  = lane & 3;          // 0..3
    const int ot   = blockIdx.x;
    const int bq   = blockIdx.y;        // 4-window group

    const __nv_bfloat16* whiB = g_whi + (size_t)(ot * 128) * 512;
    const __nv_bfloat16* wloB = g_wlo + (size_t)(ot * 128) * 512;
    const __nv_bfloat16* xhiB = g_xhi + (size_t)(bq * 256) * 512;
    const __nv_bfloat16* xloB = g_xlo + (size_t)(bq * 256) * 512;

    float acc[4][8][4];
#pragma unroll
    for (int m = 0; m < 4; m++)
#pragma unroll
        for (int n = 0; n < 8; n++)
#pragma unroll
            for (int r = 0; r < 4; r++) acc[m][n][r] = 0.f;

    auto load_chunk = [&](int c, int s) {
        const int ct = c * KC;
#pragma unroll
        for (int t = 0; t < 2; t++) {
            int slot = tid + t * 256;        // 0..511
            int row = slot >> 2, q = slot & 3;
            size_t g = (size_t)row * 512 + ct + q * 8;
            uint32_t d = row * GPAD + q * 8;
            cp16(sb + (SW_OFF(s, 0) + d) * 2, whiB + g);
            cp16(sb + (SW_OFF(s, 1) + d) * 2, wloB + g);
        }
#pragma unroll
        for (int t = 0; t < 4; t++) {
            int slot = tid + t * 256;        // 0..1023
            int row = slot >> 2, q = slot & 3;
            size_t g = (size_t)row * 512 + ct + q * 8;
            uint32_t d = row * GPAD + q * 8;
            cp16(sb + (SX_OFF(s, 0) + d) * 2, xhiB + g);
            cp16(sb + (SX_OFF(s, 1) + d) * 2, xloB + g);
        }
        asm volatile("cp.async.commit_group;" ::: "memory");
    };

    load_chunk(0, 0);
    load_chunk(1, 1);

    for (int c = 0; c < NCHUNK; c++) {
        const int s = c & 1;
        if (c < NCHUNK - 1) asm volatile("cp.async.wait_group 1;" ::: "memory");
        else                asm volatile("cp.async.wait_group 0;" ::: "memory");
        __syncthreads();

        const __nv_bfloat16* Whi = smem + SW_OFF(s, 0);
        const __nv_bfloat16* Wlo = smem + SW_OFF(s, 1);
        const __nv_bfloat16* Xhi = smem + SX_OFF(s, 0);
        const __nv_bfloat16* Xlo = smem + SX_OFF(s, 1);

#pragma unroll
        for (int ks = 0; ks < 2; ks++) {
            const int kb = ks * 16 + tig * 2;
#pragma unroll
            for (int nh = 0; nh < 2; nh++) {
                uint32_t Bh[4][2], Bl[4][2];
#pragma unroll
                for (int n = 0; n < 4; n++) {
                    int r = (n0 + (nh * 4 + n) * 8 + gid) * GPAD + kb;
                    Bh[n][0] = *(const uint32_t*)&Xhi[r];
                    Bh[n][1] = *(const uint32_t*)&Xhi[r + 8];
                    Bl[n][0] = *(const uint32_t*)&Xlo[r];
                    Bl[n][1] = *(const uint32_t*)&Xlo[r + 8];
                }
                uint32_t Ah[4][4], Al[4][4];
#pragma unroll
                for (int m = 0; m < 4; m++) {
                    int r0 = (o0 + m * 16 + gid) * GPAD + kb;
                    int r1 = r0 + 8 * GPAD;
                    Ah[m][0] = *(const uint32_t*)&Whi[r0];
                    Ah[m][1] = *(const uint32_t*)&Whi[r1];
                    Ah[m][2] = *(const uint32_t*)&Whi[r0 + 8];
                    Ah[m][3] = *(const uint32_t*)&Whi[r1 + 8];
                    Al[m][0] = *(const uint32_t*)&Wlo[r0];
                    Al[m][1] = *(const uint32_t*)&Wlo[r1];
                    Al[m][2] = *(const uint32_t*)&Wlo[r0 + 8];
                    Al[m][3] = *(const uint32_t*)&Wlo[r1 + 8];
                }
#pragma unroll
                for (int m = 0; m < 4; m++)
#pragma unroll
                    for (int n = 0; n < 4; n++)
                        mma_bf16(acc[m][nh * 4 + n],
                                 Ah[m][0], Ah[m][1], Ah[m][2], Ah[m][3],
                                 Bh[n][0], Bh[n][1]);
#pragma unroll
                for (int m = 0; m < 4; m++)
#pragma unroll
                    for (int n = 0; n < 4; n++)
                        mma_bf16(acc[m][nh * 4 + n],
                                 Ah[m][0], Ah[m][1], Ah[m][2], Ah[m][3],
                                 Bl[n][0], Bl[n][1]);
#pragma unroll
                for (int m = 0; m < 4; m++)
#pragma unroll
                    for (int n = 0; n < 4; n++)
                        mma_bf16(acc[m][nh * 4 + n],
                                 Al[m][0], Al[m][1], Al[m][2], Al[m][3],
                                 Bh[n][0], Bh[n][1]);
            }
        }

        if (c + 2 < NCHUNK) {
            __syncthreads();
            load_chunk(c + 2, s);
        }
    }

    // ---- epilogue: BN affine + store to g_qkv ----
#pragma unroll
    for (int m = 0; m < 4; m++) {
#pragma unroll
        for (int rr = 0; rr < 2; rr++) {
            int o = ot * 128 + o0 + m * 16 + gid + rr * 8;
            float sc = gg[o] * rsqrtf(gv[o] + 1e-5f);
            float sh = gb[o] - gm[o] * sc;
#pragma unroll
            for (int n = 0; n < 8; n++) {
                int col = n0 + n * 8 + 2 * tig;
                int b = bq * 4 + (col >> 6);
                int h = col & 63;
                float2 v;
                v.x = acc[m][n][rr * 2 + 0] * sc + sh;
                v.y = acc[m][n][rr * 2 + 1] * sc + sh;
                *(float2*)(g_qkv + (size_t)b * 65536 + (size_t)o * 64 + h) = v;
            }
        }
    }
}

// ---------------------------------------------------------------------------
// Kernel 2: attention per (b, g).  grid = (8 g, 512 b), 256 threads.
// qk loop uses DIAGONAL thread mapping: each warp-half owns one diagonal
// D = ty-tx (mod 16), so the Toeplitz rel loads are warp-broadcast.
// Softmax output written TRANSPOSED into dead rel rows (sT).
// ---------------------------------------------------------------------------
#define SM_V (64 * 68)
#define SM_R (128 * 68)
#define ATTN_SMEM_FLOATS (128 * 68 + 128 * 128)
#define ATTN_SMEM_BYTES (ATTN_SMEM_FLOATS * 4)

__global__ __launch_bounds__(256, 2) void attn_kernel(
    const float* __restrict__ simg, const float* __restrict__ simb,
    const float* __restrict__ simm, const float* __restrict__ simv,
    const float* __restrict__ outg, const float* __restrict__ outb,
    const float* __restrict__ outm, const float* __restrict__ outv,
    float* __restrict__ out)
{
    extern __shared__ float sm[];
    float* sQ = sm;                 // rows 0..31
    float* sK = sm + 32 * 68;       // rows 32..63
    float* sS = sm;                 // OVERLAY (pre-softmax sim) after sync
    float* sV = sm + SM_V;
    float* sR = sm + SM_R;
    float* sT = sm + SM_R;          // OVERLAY: transposed softmax output
    const uint32_t sb = smem_u32(sm);

    const int g   = blockIdx.x;
    const int b   = blockIdx.y;
    const int n   = b >> 6;
    const int wi  = b & 63;
    const int tid = threadIdx.x;

    // Load rel table (padded, contiguous) via cp.async
#pragma unroll
    for (int t = 0; t < 16; t++) {
        int idx = (tid + t * 256) * 4;     // 0..16380
        cp16(sb + (SM_R + idx) * 4, g_relp + idx);
    }
    // Load q/k/v tiles from the qkv scratch via cp.async
    const float* base = g_qkv + (size_t)b * 65536 + (size_t)g * 128 * 64;
#pragma unroll
    for (int t = 0; t < 8; t++) {
        int idx = (tid + t * 256) * 4;     // element index, 0..8188
        int cc = idx >> 6;
        int h  = idx & 63;
        uint32_t dst = (cc < 64) ? (cc * 68 + h)
                                 : (SM_V + (cc - 64) * 68 + h);
        cp16(sb + dst * 4, base + idx);
    }
    asm volatile("cp.async.commit_group;" ::: "memory");
    asm volatile("cp.async.wait_group 0;" ::: "memory");
    __syncthreads();

    // --------------- sim = BN(qk) + BN(qr) + BN(kr) ---------------
    // Diagonal mapping: D constant per warp-half -> rel loads broadcast.
    const int txd = tid & 15;                       // j tile
    const int Dd  = (tid >> 4);                     // 0..15 diagonal class
    const int tyd = (txd + Dd) & 15;                // i tile
    const int i0 = tyd * 4;
    const int j0 = txd * 4;
    const int dq0 = i0 - j0 + 60;   // multiple of 4, in [0, 120]
    const int dk0 = j0 - i0 + 60;

    float aqk[4][4], aqr[4][4], akr[4][4];
#pragma unroll
    for (int a = 0; a < 4; a++)
#pragma unroll
        for (int c = 0; c < 4; c++) { aqk[a][c] = 0.f; aqr[a][c] = 0.f; akr[a][c] = 0.f; }

#pragma unroll 4
    for (int c = 0; c < 32; c++) {
        float4 qv4 = *(const float4*)&sQ[c * 68 + i0];
        float4 kv4 = *(const float4*)&sK[c * 68 + j0];
        float4 rq0 = *(const float4*)&sR[c * 128 + dq0];
        float4 rq1 = *(const float4*)&sR[c * 128 + dq0 + 4];
        float4 rk0 = *(const float4*)&sR[(32 + c) * 128 + dk0];
        float4 rk1 = *(const float4*)&sR[(32 + c) * 128 + dk0 + 4];
        float qv[4] = {qv4.x, qv4.y, qv4.z, qv4.w};
        float kv[4] = {kv4.x, kv4.y, kv4.z, kv4.w};
        float rq[8] = {rq0.x, rq0.y, rq0.z, rq0.w, rq1.x, rq1.y, rq1.z, rq1.w};
        float rk[8] = {rk0.x, rk0.y, rk0.z, rk0.w, rk1.x, rk1.y, rk1.z, rk1.w};
#pragma unroll
        for (int ii = 0; ii < 4; ii++)
#pragma unroll
            for (int jj = 0; jj < 4; jj++) {
                aqk[ii][jj] = fmaf(qv[ii], kv[jj], aqk[ii][jj]);
                aqr[ii][jj] = fmaf(qv[ii], rq[ii - jj + 3], aqr[ii][jj]);
                akr[ii][jj] = fmaf(kv[jj], rk[jj - ii + 3], akr[ii][jj]);
            }
    }

    const float s_qk = simg[g]      * rsqrtf(simv[g]      + 1e-5f);
    const float s_qr = simg[8 + g]  * rsqrtf(simv[8 + g]  + 1e-5f);
    const float s_kr = simg[16 + g] * rsqrtf(simv[16 + g] + 1e-5f);
    const float sh_sum = (simb[g]      - simm[g]      * s_qk)
                       + (simb[8 + g]  - simm[8 + g]  * s_qr)
                       + (simb[16 + g] - simm[16 + g] * s_kr);

    __syncthreads();   // all reads of q/k (and rel rows 0..63) done
#pragma unroll
    for (int ii = 0; ii < 4; ii++)
#pragma unroll
        for (int jj = 0; jj < 4; jj++)
            sS[(i0 + ii) * 68 + j0 + jj] =
                s_qk * aqk[ii][jj] + s_qr * aqr[ii][jj] + s_kr * akr[ii][jj] + sh_sum;
    __syncthreads();

    // ---- softmax over j; output written transposed into sT[j][i] ----
    {
        int warp = tid >> 5, lane = tid & 31;
#pragma unroll
        for (int r = 0; r < 8; r++) {
            int i = warp * 8 + r;
            float a0 = sS[i * 68 + lane];
            float a1 = sS[i * 68 + lane + 32];
            float mx = fmaxf(a0, a1);
#pragma unroll
            for (int off = 16; off > 0; off >>= 1)
                mx = fmaxf(mx, __shfl_xor_sync(0xffffffffu, mx, off));
            float e0 = __expf(a0 - mx);
            float e1 = __expf(a1 - mx);
            float s = e0 + e1;
#pragma unroll
            for (int off = 16; off > 0; off >>= 1)
                s += __shfl_xor_sync(0xffffffffu, s, off);
            float inv = 1.0f / s;
            sT[lane * 68 + i]        = e0 * inv;   // sim[i][lane]
            sT[(lane + 32) * 68 + i] = e1 * inv;   // sim[i][lane+32]
        }
    }
    __syncthreads();

    // --------------- sv / sve (transposed sim reads, conflict-free) -------
    const int tx  = tid & 15;
    const int ty  = tid >> 4;
    const int c0  = ty * 4;
    const int ii0 = tx * 4;
    float asv[4][4], asve[4][4];
#pragma unroll
    for (int a = 0; a < 4; a++)
#pragma unroll
        for (int c = 0; c < 4; c++) { asv[a][c] = 0.f; asve[a][c] = 0.f; }

    // carry: rcar[cc] holds rel[(64+c0+cc)*128 + ii0 - 4*jq + 64 .. +67]
    float4 rcar[4];
#pragma unroll
    for (int cc = 0; cc < 4; cc++)
        rcar[cc] = *(const float4*)&sR[(64 + c0 + cc) * 128 + ii0 + 64];

#pragma unroll 2
    for (int jq = 0; jq < 16; jq++) {
        // sjf[jj][t] = sim[ii0+t][4*jq+jj]  (float4 over i from sT)
        float sjf[4][4];
#pragma unroll
        for (int jj = 0; jj < 4; jj++) {
            float4 v = *(const float4*)&sT[(jq * 4 + jj) * 68 + ii0];
            sjf[jj][0] = v.x; sjf[jj][1] = v.y; sjf[jj][2] = v.z; sjf[jj][3] = v.w;
        }
        float4 vv[4];
#pragma unroll
        for (int t = 0; t < 4; t++) vv[t] = *(const float4*)&sV[(c0 + t) * 68 + jq * 4];

#pragma unroll
        for (int cc = 0; cc < 4; cc++) {
            float4 r0 = *(const float4*)&sR[(64 + c0 + cc) * 128 + ii0 - jq * 4 + 60];
            float rv8[8] = {r0.x, r0.y, r0.z, r0.w,
                            rcar[cc].x, rcar[cc].y, rcar[cc].z, rcar[cc].w};
#pragma unroll
            for (int t = 0; t < 4; t++) {
                float a = asv[cc][t];
                a = fmaf(sjf[0][t], vv[cc].x, a);
                a = fmaf(sjf[1][t], vv[cc].y, a);
                a = fmaf(sjf[2][t], vv[cc].z, a);
                a = fmaf(sjf[3][t], vv[cc].w, a);
                asv[cc][t] = a;
                float e = asve[cc][t];
                e = fmaf(sjf[0][t], rv8[t + 3], e);
                e = fmaf(sjf[1][t], rv8[t + 2], e);
                e = fmaf(sjf[2][t], rv8[t + 1], e);
                e = fmaf(sjf[3][t], rv8[t + 0], e);
                asve[cc][t] = e;
            }
            rcar[cc] = r0;
        }
    }

    // --------------- out BN + interleaved sum, transpose via smem ---------------
    float res[4][4];
#pragma unroll
    for (int cc = 0; cc < 4; cc++) {
        int c  = c0 + cc;
        int o0 = g * 128 + 2 * c;
        float sc0 = outg[o0]     * rsqrtf(outv[o0]     + 1e-5f);
        float sh0 = outb[o0]     - outm[o0]     * sc0;
        float sc1 = outg[o0 + 1] * rsqrtf(outv[o0 + 1] + 1e-5f);
        float sh1 = outb[o0 + 1] - outm[o0 + 1] * sc1;
#pragma unroll
        for (int t = 0; t < 4; t++)
            res[cc][t] = sc0 * asv[cc][t] + sc1 * asve[cc][t] + sh0 + sh1;
    }
    __syncthreads();
#pragma unroll
    for (int cc = 0; cc < 4; cc++)
#pragma unroll
        for (int t = 0; t < 4; t++)
            sS[(c0 + cc) * 68 + ii0 + t] = res[cc][t];
    __syncthreads();

    // coalesced write: out[(wi*64+i)*4096 + n*512 + g*64 + c]
    float* ob = out + (size_t)(wi * 64) * 4096 + n * 512 + g * 64;
    {
        int c = tid & 63;
        int ib = tid >> 6;     // 0..3
#pragma unroll
        for (int r = 0; r < 16; r++) {
            int i = ib + r * 4;
            ob[(size_t)i * 4096 + c] = sS[c * 68 + i];
        }
    }
}

// ---------------------------------------------------------------------------
extern "C" void kernel_launch(void* const* d_in, const int* in_sizes, int n_in,
                              void* d_out, int out_size)
{
    const float* x     = (const float*)d_in[0];
    const float* qkv_w = (const float*)d_in[1];
    const float* rel   = (const float*)d_in[2];
    const float* qkv_g = (const float*)d_in[3];
    const float* qkv_b = (const float*)d_in[4];
    const float* qkv_m = (const float*)d_in[5];
    const float* qkv_v = (const float*)d_in[6];
    const float* sim_g = (const float*)d_in[7];
    const float* sim_b = (const float*)d_in[8];
    const float* sim_m = (const float*)d_in[9];
    const float* sim_v = (const float*)d_in[10];
    const float* out_g = (const float*)d_in[11];
    const float* out_b = (const float*)d_in[12];
    const float* out_m = (const float*)d_in[13];
    const float* out_v = (const float*)d_in[14];
    float* out = (float*)d_out;

    // 33792*128 float4 slots for X/W split + 16384 threads for rel pad
    int total_threads = 33792 * 128 + 128 * 128;
    split_prep<<<(total_threads + 255) / 256, 256>>>(x, qkv_w, rel);

    cudaFuncSetAttribute(qkv_gemm_mma,
                         cudaFuncAttributeMaxDynamicSharedMemorySize,
                         GEMM_SMEM_BYTES);
    qkv_gemm_mma<<<dim3(8, 128), 256, GEMM_SMEM_BYTES>>>(
        qkv_g, qkv_b, qkv_m, qkv_v);

    cudaFuncSetAttribute(attn_kernel,
                         cudaFuncAttributeMaxDynamicSharedMemorySize,
                         ATTN_SMEM_BYTES);
    attn_kernel<<<dim3(8, 512), 256, ATTN_SMEM_BYTES>>>(
        sim_g, sim_b, sim_m, sim_v,
        out_g, out_b, out_m, out_v, out);
}

// round 14
// speedup vs baseline: 1.0691x; 1.0348x over previous
#include <cuda_runtime.h>
#include <cuda_bf16.h>
#include <cstdint>

// Problem constants
#define L_DIM 4096
#define N_DIM 8
#define C_DIM 512
#define OUT_DIM 512
#define G_DIM 8
#define KS_DIM 64
#define W_DIM 64          // L / KS
#define B_DIM 512         // N * W

// Scratch: qkv intermediate [B][1024][64] (BN already applied)
__device__ float g_qkv[(size_t)B_DIM * 1024 * 64];
// Split bf16 copies (X relaid to [b*64+h][c], W as [o][c])
__device__ __nv_bfloat16 g_xhi[(size_t)32768 * 512];
__device__ __nv_bfloat16 g_xlo[(size_t)32768 * 512];
__device__ __nv_bfloat16 g_whi[(size_t)1024 * 512];
__device__ __nv_bfloat16 g_wlo[(size_t)1024 * 512];
// Padded relative table: row stride 128 (float4-aligned rows)
__device__ float g_relp[128 * 128];

// ===========================================================================
// helpers
// ===========================================================================
__device__ __forceinline__ uint32_t smem_u32(const void* p) {
    uint32_t a;
    asm("{ .reg .u64 t; cvta.to.shared.u64 t, %1; cvt.u32.u64 %0, t; }"
        : "=r"(a) : "l"(p));
    return a;
}

__device__ __forceinline__ void cp16(uint32_t dst, const void* src) {
    asm volatile("cp.async.ca.shared.global [%0], [%1], 16;"
                 :: "r"(dst), "l"(src) : "memory");
}

// hi = truncate-to-bf16(x) (bitwise), lo = rn_bf16(x - hi).
__device__ __forceinline__ void split_store4(
    float4 a, __nv_bfloat16* hi, __nv_bfloat16* lo, size_t off)
{
    uint32_t x = __float_as_uint(a.x), y = __float_as_uint(a.y);
    uint32_t z = __float_as_uint(a.z), w = __float_as_uint(a.w);
    uint32_t h01 = __byte_perm(x, y, 0x7632);
    uint32_t h23 = __byte_perm(z, w, 0x7632);
    float lx = a.x - __uint_as_float(x & 0xFFFF0000u);
    float ly = a.y - __uint_as_float(y & 0xFFFF0000u);
    float lz = a.z - __uint_as_float(z & 0xFFFF0000u);
    float lw = a.w - __uint_as_float(w & 0xFFFF0000u);
    uint32_t l01, l23;
    asm("cvt.rn.bf16x2.f32 %0, %1, %2;" : "=r"(l01) : "f"(ly), "f"(lx));
    asm("cvt.rn.bf16x2.f32 %0, %1, %2;" : "=r"(l23) : "f"(lw), "f"(lz));
    *(uint2*)(hi + off) = make_uint2(h01, h23);
    *(uint2*)(lo + off) = make_uint2(l01, l23);
}

__device__ __forceinline__ void mma_bf16(
    float d[4], uint32_t a0, uint32_t a1, uint32_t a2, uint32_t a3,
    uint32_t b0, uint32_t b1)
{
    asm volatile(
        "mma.sync.aligned.m16n8k16.row.col.f32.bf16.bf16.f32 "
        "{%0,%1,%2,%3}, {%4,%5,%6,%7}, {%8,%9}, {%0,%1,%2,%3};"
        : "+f"(d[0]), "+f"(d[1]), "+f"(d[2]), "+f"(d[3])
        : "r"(a0), "r"(a1), "r"(a2), "r"(a3), "r"(b0), "r"(b1));
}

// ===========================================================================
// Kernel 0: split X and W into bf16 hi/lo global scratch; also pad rel.
// ===========================================================================
__global__ __launch_bounds__(256) void split_prep(
    const float* __restrict__ x, const float* __restrict__ w,
    const float* __restrict__ rel)
{
    int idx = blockIdx.x * 256 + threadIdx.x;   // one float4 each
    int row = idx >> 7;
    int q   = idx & 127;
    if (row < 32768) {
        int b = row >> 6, h = row & 63;
        int n = b >> 6,  wi = b & 63;
        float4 a = *(const float4*)(x + (size_t)(wi * 64 + h) * 4096
                                      + n * 512 + q * 4);
        split_store4(a, g_xhi, g_xlo, (size_t)row * 512 + q * 4);
    } else if (row < 33792) {
        int o = row - 32768;
        float4 a = *(const float4*)(w + (size_t)o * 512 + q * 4);
        split_store4(a, g_whi, g_wlo, (size_t)o * 512 + q * 4);
    }
    // rel pad handled by dedicated tail blocks:
    int tidg = blockIdx.x * 256 + threadIdx.x - 33792 * 128;
    if (tidg >= 0 && tidg < 128 * 128) {
        int r = tidg >> 7, d = tidg & 127;
        g_relp[tidg] = (d < 127) ? rel[r * 127 + d] : 0.f;
    }
}

// ===========================================================================
// Kernel 1: QKV GEMM (exact R10 config, 282us measured).
//  D[o(128), n(256 = 4 windows x 64 h)] ; grid = (8 ot, 128 bq), 256 thr.
//  K = 512 in 16 chunks of 32, 2-stage double buffer, GPAD=40.
// ===========================================================================
#define GPAD 40   // bf16 row stride
#define KC 32
#define NCHUNK 16

// smem offsets in bf16 units
#define SW_OFF(s, hl) (((s) * 2 + (hl)) * 128 * GPAD)
#define SX_OFF(s, hl) (4 * 128 * GPAD + ((s) * 2 + (hl)) * 256 * GPAD)
#define GEMM_SMEM_BF16 (4 * 128 * GPAD + 4 * 256 * GPAD)
#define GEMM_SMEM_BYTES (GEMM_SMEM_BF16 * 2)

__global__ __launch_bounds__(256, 1) void qkv_gemm_mma(
    const float* __restrict__ gg, const float* __restrict__ gb,
    const float* __restrict__ gm, const float* __restrict__ gv)
{
    extern __shared__ __nv_bfloat16 smem[];
    const uint32_t sb = smem_u32(smem);

    const int tid  = threadIdx.x;
    const int lane = tid & 31;
    const int wid  = tid >> 5;
    const int wm   = wid >> 2;          // 0..1
    const int wn   = wid & 3;           // 0..3
    const int o0   = wm * 64;
    const int n0   = wn * 64;
    const int gid  = lane >> 2;         // 0..7
    const int tig  = lane & 3;          // 0..3
    const int ot   = blockIdx.x;
    const int bq   = blockIdx.y;        // 4-window group

    const __nv_bfloat16* whiB = g_whi + (size_t)(ot * 128) * 512;
    const __nv_bfloat16* wloB = g_wlo + (size_t)(ot * 128) * 512;
    const __nv_bfloat16* xhiB = g_xhi + (size_t)(bq * 256) * 512;
    const __nv_bfloat16* xloB = g_xlo + (size_t)(bq * 256) * 512;

    float acc[4][8][4];
#pragma unroll
    for (int m = 0; m < 4; m++)
#pragma unroll
        for (int n = 0; n < 8; n++)
#pragma unroll
            for (int r = 0; r < 4; r++) acc[m][n][r] = 0.f;

    auto load_chunk = [&](int c, int s) {
        const int ct = c * KC;
#pragma unroll
        for (int t = 0; t < 2; t++) {
            int slot = tid + t * 256;        // 0..511
            int row = slot >> 2, q = slot & 3;
            size_t g = (size_t)row * 512 + ct + q * 8;
            uint32_t d = row * GPAD + q * 8;
            cp16(sb + (SW_OFF(s, 0) + d) * 2, whiB + g);
            cp16(sb + (SW_OFF(s, 1) + d) * 2, wloB + g);
        }
#pragma unroll
        for (int t = 0; t < 4; t++) {
            int slot = tid + t * 256;        // 0..1023
            int row = slot >> 2, q = slot & 3;
            size_t g = (size_t)row * 512 + ct + q * 8;
            uint32_t d = row * GPAD + q * 8;
            cp16(sb + (SX_OFF(s, 0) + d) * 2, xhiB + g);
            cp16(sb + (SX_OFF(s, 1) + d) * 2, xloB + g);
        }
        asm volatile("cp.async.commit_group;" ::: "memory");
    };

    load_chunk(0, 0);
    load_chunk(1, 1);

    for (int c = 0; c < NCHUNK; c++) {
        const int s = c & 1;
        if (c < NCHUNK - 1) asm volatile("cp.async.wait_group 1;" ::: "memory");
        else                asm volatile("cp.async.wait_group 0;" ::: "memory");
        __syncthreads();

        const __nv_bfloat16* Whi = smem + SW_OFF(s, 0);
        const __nv_bfloat16* Wlo = smem + SW_OFF(s, 1);
        const __nv_bfloat16* Xhi = smem + SX_OFF(s, 0);
        const __nv_bfloat16* Xlo = smem + SX_OFF(s, 1);

#pragma unroll
        for (int ks = 0; ks < 2; ks++) {
            const int kb = ks * 16 + tig * 2;
#pragma unroll
            for (int nh = 0; nh < 2; nh++) {
                uint32_t Bh[4][2], Bl[4][2];
#pragma unroll
                for (int n = 0; n < 4; n++) {
                    int r = (n0 + (nh * 4 + n) * 8 + gid) * GPAD + kb;
                    Bh[n][0] = *(const uint32_t*)&Xhi[r];
                    Bh[n][1] = *(const uint32_t*)&Xhi[r + 8];
                    Bl[n][0] = *(const uint32_t*)&Xlo[r];
                    Bl[n][1] = *(const uint32_t*)&Xlo[r + 8];
                }
                uint32_t Ah[4][4], Al[4][4];
#pragma unroll
                for (int m = 0; m < 4; m++) {
                    int r0 = (o0 + m * 16 + gid) * GPAD + kb;
                    int r1 = r0 + 8 * GPAD;
                    Ah[m][0] = *(const uint32_t*)&Whi[r0];
                    Ah[m][1] = *(const uint32_t*)&Whi[r1];
                    Ah[m][2] = *(const uint32_t*)&Whi[r0 + 8];
                    Ah[m][3] = *(const uint32_t*)&Whi[r1 + 8];
                    Al[m][0] = *(const uint32_t*)&Wlo[r0];
                    Al[m][1] = *(const uint32_t*)&Wlo[r1];
                    Al[m][2] = *(const uint32_t*)&Wlo[r0 + 8];
                    Al[m][3] = *(const uint32_t*)&Wlo[r1 + 8];
                }
#pragma unroll
                for (int m = 0; m < 4; m++)
#pragma unroll
                    for (int n = 0; n < 4; n++)
                        mma_bf16(acc[m][nh * 4 + n],
                                 Ah[m][0], Ah[m][1], Ah[m][2], Ah[m][3],
                                 Bh[n][0], Bh[n][1]);
#pragma unroll
                for (int m = 0; m < 4; m++)
#pragma unroll
                    for (int n = 0; n < 4; n++)
                        mma_bf16(acc[m][nh * 4 + n],
                                 Ah[m][0], Ah[m][1], Ah[m][2], Ah[m][3],
                                 Bl[n][0], Bl[n][1]);
#pragma unroll
                for (int m = 0; m < 4; m++)
#pragma unroll
                    for (int n = 0; n < 4; n++)
                        mma_bf16(acc[m][nh * 4 + n],
                                 Al[m][0], Al[m][1], Al[m][2], Al[m][3],
                                 Bh[n][0], Bh[n][1]);
            }
        }

        if (c + 2 < NCHUNK) {
            __syncthreads();
            load_chunk(c + 2, s);
        }
    }

    // ---- epilogue: BN affine + store to g_qkv ----
#pragma unroll
    for (int m = 0; m < 4; m++) {
#pragma unroll
        for (int rr = 0; rr < 2; rr++) {
            int o = ot * 128 + o0 + m * 16 + gid + rr * 8;
            float sc = gg[o] * rsqrtf(gv[o] + 1e-5f);
            float sh = gb[o] - gm[o] * sc;
#pragma unroll
            for (int n = 0; n < 8; n++) {
                int col = n0 + n * 8 + 2 * tig;
                int b = bq * 4 + (col >> 6);
                int h = col & 63;
                float2 v;
                v.x = acc[m][n][rr * 2 + 0] * sc + sh;
                v.y = acc[m][n][rr * 2 + 1] * sc + sh;
                *(float2*)(g_qkv + (size_t)b * 65536 + (size_t)o * 64 + h) = v;
            }
        }
    }
}

// ---------------------------------------------------------------------------
// Kernel 2: attention per (b, g).  grid = (8 g, 512 b), 256 threads.
// Exact R9/R10 compute. Prologue split into two cp.async groups:
//  group A (q/k + rel rows 0..63) gates the qk loop;
//  group B (v + rel rows 64..127) is waited only before the sv/sve phase.
// ---------------------------------------------------------------------------
#define SM_V (64 * 68)
#define SM_R (128 * 68)
#define ATTN_SMEM_FLOATS (128 * 68 + 128 * 128)
#define ATTN_SMEM_BYTES (ATTN_SMEM_FLOATS * 4)

__global__ __launch_bounds__(256, 2) void attn_kernel(
    const float* __restrict__ simg, const float* __restrict__ simb,
    const float* __restrict__ simm, const float* __restrict__ simv,
    const float* __restrict__ outg, const float* __restrict__ outb,
    const float* __restrict__ outm, const float* __restrict__ outv,
    float* __restrict__ out)
{
    extern __shared__ float sm[];
    float* sQ = sm;                 // rows 0..31
    float* sK = sm + 32 * 68;       // rows 32..63
    float* sS = sm;                 // OVERLAY (pre-softmax sim) after sync
    float* sV = sm + SM_V;
    float* sR = sm + SM_R;
    float* sT = sm + SM_R;          // OVERLAY: transposed softmax output in
                                    // dead rel rows 0..63 (stride 68)
    const uint32_t sb = smem_u32(sm);

    const int g   = blockIdx.x;
    const int b   = blockIdx.y;
    const int n   = b >> 6;
    const int wi  = b & 63;
    const int tid = threadIdx.x;
    const int tx  = tid & 15;
    const int ty  = tid >> 4;

    const float* base = g_qkv + (size_t)b * 65536 + (size_t)g * 128 * 64;

    // ---- GROUP A: q/k tiles (rows 0..63) + rel rows 0..63 ----
#pragma unroll
    for (int t = 0; t < 4; t++) {
        int idx = (tid + t * 256) * 4;     // 0..4092 (q/k region)
        int cc = idx >> 6;
        int h  = idx & 63;
        cp16(sb + (cc * 68 + h) * 4, base + idx);
    }
#pragma unroll
    for (int t = 0; t < 8; t++) {
        int idx = (tid + t * 256) * 4;     // 0..8188 (rel rows 0..63)
        cp16(sb + (SM_R + idx) * 4, g_relp + idx);
    }
    asm volatile("cp.async.commit_group;" ::: "memory");

    // ---- GROUP B: v tiles (rows 64..127) + rel rows 64..127 ----
#pragma unroll
    for (int t = 0; t < 4; t++) {
        int idx = 4096 + (tid + t * 256) * 4;  // 4096..8188 (v region)
        int cc = idx >> 6;
        int h  = idx & 63;
        cp16(sb + (SM_V + (cc - 64) * 68 + h) * 4, base + idx);
    }
#pragma unroll
    for (int t = 0; t < 8; t++) {
        int idx = 8192 + (tid + t * 256) * 4;  // rel rows 64..127
        cp16(sb + (SM_R + idx) * 4, g_relp + idx);
    }
    asm volatile("cp.async.commit_group;" ::: "memory");

    // Wait only for GROUP A before the qk phase.
    asm volatile("cp.async.wait_group 1;" ::: "memory");
    __syncthreads();

    // --------------- sim = BN(qk) + BN(qr) + BN(kr) ---------------
    const int i0 = ty * 4;
    const int j0 = tx * 4;
    const int dq0 = i0 - j0 + 60;
    const int dk0 = j0 - i0 + 60;

    float aqk[4][4], aqr[4][4], akr[4][4];
#pragma unroll
    for (int a = 0; a < 4; a++)
#pragma unroll
        for (int c = 0; c < 4; c++) { aqk[a][c] = 0.f; aqr[a][c] = 0.f; akr[a][c] = 0.f; }

#pragma unroll 4
    for (int c = 0; c < 32; c++) {
        float4 qv4 = *(const float4*)&sQ[c * 68 + i0];
        float4 kv4 = *(const float4*)&sK[c * 68 + j0];
        float4 rq0 = *(const float4*)&sR[c * 128 + dq0];
        float4 rq1 = *(const float4*)&sR[c * 128 + dq0 + 4];
        float4 rk0 = *(const float4*)&sR[(32 + c) * 128 + dk0];
        float4 rk1 = *(const float4*)&sR[(32 + c) * 128 + dk0 + 4];
        float qv[4] = {qv4.x, qv4.y, qv4.z, qv4.w};
        float kv[4] = {kv4.x, kv4.y, kv4.z, kv4.w};
        float rq[8] = {rq0.x, rq0.y, rq0.z, rq0.w, rq1.x, rq1.y, rq1.z, rq1.w};
        float rk[8] = {rk0.x, rk0.y, rk0.z, rk0.w, rk1.x, rk1.y, rk1.z, rk1.w};
#pragma unroll
        for (int ii = 0; ii < 4; ii++)
#pragma unroll
            for (int jj = 0; jj < 4; jj++) {
                aqk[ii][jj] = fmaf(qv[ii], kv[jj], aqk[ii][jj]);
                aqr[ii][jj] = fmaf(qv[ii], rq[ii - jj + 3], aqr[ii][jj]);
                akr[ii][jj] = fmaf(kv[jj], rk[jj - ii + 3], akr[ii][jj]);
            }
    }

    const float s_qk = simg[g]      * rsqrtf(simv[g]      + 1e-5f);
    const float s_qr = simg[8 + g]  * rsqrtf(simv[8 + g]  + 1e-5f);
    const float s_kr = simg[16 + g] * rsqrtf(simv[16 + g] + 1e-5f);
    const float sh_sum = (simb[g]      - simm[g]      * s_qk)
                       + (simb[8 + g]  - simm[8 + g]  * s_qr)
                       + (simb[16 + g] - simm[16 + g] * s_kr);

    __syncthreads();   // all reads of q/k (and rel rows 0..63) done
#pragma unroll
    for (int ii = 0; ii < 4; ii++)
#pragma unroll
        for (int jj = 0; jj < 4; jj++)
            sS[(i0 + ii) * 68 + j0 + jj] =
                s_qk * aqk[ii][jj] + s_qr * aqr[ii][jj] + s_kr * akr[ii][jj] + sh_sum;
    __syncthreads();

    // ---- softmax over j; output written transposed into sT[j][i] ----
    {
        int warp = tid >> 5, lane = tid & 31;
#pragma unroll
        for (int r = 0; r < 8; r++) {
            int i = warp * 8 + r;
            float a0 = sS[i * 68 + lane];
            float a1 = sS[i * 68 + lane + 32];
            float mx = fmaxf(a0, a1);
#pragma unroll
            for (int off = 16; off > 0; off >>= 1)
                mx = fmaxf(mx, __shfl_xor_sync(0xffffffffu, mx, off));
            float e0 = __expf(a0 - mx);
            float e1 = __expf(a1 - mx);
            float s = e0 + e1;
#pragma unroll
            for (int off = 16; off > 0; off >>= 1)
                s += __shfl_xor_sync(0xffffffffu, s, off);
            float inv = 1.0f / s;
            sT[lane * 68 + i]        = e0 * inv;   // sim[i][lane]
            sT[(lane + 32) * 68 + i] = e1 * inv;   // sim[i][lane+32]
        }
    }
    // Wait for GROUP B (v + rel rows 64..127) before the sv/sve phase.
    asm volatile("cp.async.wait_group 0;" ::: "memory");
    __syncthreads();

    // --------------- sv / sve (transposed sim reads, conflict-free) -------
    const int c0  = ty * 4;
    const int ii0 = tx * 4;
    float asv[4][4], asve[4][4];
#pragma unroll
    for (int a = 0; a < 4; a++)
#pragma unroll
        for (int c = 0; c < 4; c++) { asv[a][c] = 0.f; asve[a][c] = 0.f; }

    // carry: rcar[cc] holds rel[(64+c0+cc)*128 + ii0 - 4*jq + 64 .. +67]
    float4 rcar[4];
#pragma unroll
    for (int cc = 0; cc < 4; cc++)
        rcar[cc] = *(const float4*)&sR[(64 + c0 + cc) * 128 + ii0 + 64];

#pragma unroll 2
    for (int jq = 0; jq < 16; jq++) {
        // sjf[jj][t] = sim[ii0+t][4*jq+jj]  (float4 over i from sT)
        float sjf[4][4];
#pragma unroll
        for (int jj = 0; jj < 4; jj++) {
            float4 v = *(const float4*)&sT[(jq * 4 + jj) * 68 + ii0];
            sjf[jj][0] = v.x; sjf[jj][1] = v.y; sjf[jj][2] = v.z; sjf[jj][3] = v.w;
        }
        float4 vv[4];
#pragma unroll
        for (int t = 0; t < 4; t++) vv[t] = *(const float4*)&sV[(c0 + t) * 68 + jq * 4];

#pragma unroll
        for (int cc = 0; cc < 4; cc++) {
            float4 r0 = *(const float4*)&sR[(64 + c0 + cc) * 128 + ii0 - jq * 4 + 60];
            float rv8[8] = {r0.x, r0.y, r0.z, r0.w,
                            rcar[cc].x, rcar[cc].y, rcar[cc].z, rcar[cc].w};
#pragma unroll
            for (int t = 0; t < 4; t++) {
                float a = asv[cc][t];
                a = fmaf(sjf[0][t], vv[cc].x, a);
                a = fmaf(sjf[1][t], vv[cc].y, a);
                a = fmaf(sjf[2][t], vv[cc].z, a);
                a = fmaf(sjf[3][t], vv[cc].w, a);
                asv[cc][t] = a;
                float e = asve[cc][t];
                e = fmaf(sjf[0][t], rv8[t + 3], e);
                e = fmaf(sjf[1][t], rv8[t + 2], e);
                e = fmaf(sjf[2][t], rv8[t + 1], e);
                e = fmaf(sjf[3][t], rv8[t + 0], e);
                asve[cc][t] = e;
            }
            rcar[cc] = r0;
        }
    }

    // --------------- out BN + interleaved sum, transpose via smem ---------------
    float res[4][4];
#pragma unroll
    for (int cc = 0; cc < 4; cc++) {
        int c  = c0 + cc;
        int o0 = g * 128 + 2 * c;
        float sc0 = outg[o0]     * rsqrtf(outv[o0]     + 1e-5f);
        float sh0 = outb[o0]     - outm[o0]     * sc0;
        float sc1 = outg[o0 + 1] * rsqrtf(outv[o0 + 1] + 1e-5f);
        float sh1 = outb[o0 + 1] - outm[o0 + 1] * sc1;
#pragma unroll
        for (int t = 0; t < 4; t++)
            res[cc][t] = sc0 * asv[cc][t] + sc1 * asve[cc][t] + sh0 + sh1;
    }
    __syncthreads();
#pragma unroll
    for (int cc = 0; cc < 4; cc++)
#pragma unroll
        for (int t = 0; t < 4; t++)
            sS[(c0 + cc) * 68 + ii0 + t] = res[cc][t];
    __syncthreads();

    // coalesced write: out[(wi*64+i)*4096 + n*512 + g*64 + c]
    float* ob = out + (size_t)(wi * 64) * 4096 + n * 512 + g * 64;
    {
        int c = tid & 63;
        int ib = tid >> 6;     // 0..3
#pragma unroll
        for (int r = 0; r < 16; r++) {
            int i = ib + r * 4;
            ob[(size_t)i * 4096 + c] = sS[c * 68 + i];
        }
    }
}

// ---------------------------------------------------------------------------
extern "C" void kernel_launch(void* const* d_in, const int* in_sizes, int n_in,
                              void* d_out, int out_size)
{
    const float* x     = (const float*)d_in[0];
    const float* qkv_w = (const float*)d_in[1];
    const float* rel   = (const float*)d_in[2];
    const float* qkv_g = (const float*)d_in[3];
    const float* qkv_b = (const float*)d_in[4];
    const float* qkv_m = (const float*)d_in[5];
    const float* qkv_v = (const float*)d_in[6];
    const float* sim_g = (const float*)d_in[7];
    const float* sim_b = (const float*)d_in[8];
    const float* sim_m = (const float*)d_in[9];
    const float* sim_v = (const float*)d_in[10];
    const float* out_g = (const float*)d_in[11];
    const float* out_b = (const float*)d_in[12];
    const float* out_m = (const float*)d_in[13];
    const float* out_v = (const float*)d_in[14];
    float* out = (float*)d_out;

    // 33792*128 float4 slots for X/W split + 16384 threads for rel pad
    int total_threads = 33792 * 128 + 128 * 128;
    split_prep<<<(total_threads + 255) / 256, 256>>>(x, qkv_w, rel);

    cudaFuncSetAttribute(qkv_gemm_mma,
                         cudaFuncAttributeMaxDynamicSharedMemorySize,
                         GEMM_SMEM_BYTES);
    qkv_gemm_mma<<<dim3(8, 128), 256, GEMM_SMEM_BYTES>>>(
        qkv_g, qkv_b, qkv_m, qkv_v);

    cudaFuncSetAttribute(attn_kernel,
                         cudaFuncAttributeMaxDynamicSharedMemorySize,
                         ATTN_SMEM_BYTES);
    attn_kernel<<<dim3(8, 512), 256, ATTN_SMEM_BYTES>>>(
        sim_g, sim_b, sim_m, sim_v,
        out_g, out_b, out_m, out_v, out);
}

// round 15
// speedup vs baseline: 1.0812x; 1.0114x over previous
#include <cuda_runtime.h>
#include <cuda_bf16.h>
#include <cstdint>

// Problem constants
#define L_DIM 4096
#define N_DIM 8
#define C_DIM 512
#define OUT_DIM 512
#define G_DIM 8
#define KS_DIM 64
#define W_DIM 64          // L / KS
#define B_DIM 512         // N * W

// Scratch: qkv intermediate [B][1024][64] (BN already applied)
__device__ float g_qkv[(size_t)B_DIM * 1024 * 64];
// Split bf16 copies (X relaid to [b*64+h][c], W as [o][c])
__device__ __nv_bfloat16 g_xhi[(size_t)32768 * 512];
__device__ __nv_bfloat16 g_xlo[(size_t)32768 * 512];
__device__ __nv_bfloat16 g_whi[(size_t)1024 * 512];
__device__ __nv_bfloat16 g_wlo[(size_t)1024 * 512];
// Padded relative table: row stride 128 (float4-aligned rows)
__device__ float g_relp[128 * 128];

// ===========================================================================
// helpers
// ===========================================================================
__device__ __forceinline__ uint32_t smem_u32(const void* p) {
    uint32_t a;
    asm("{ .reg .u64 t; cvta.to.shared.u64 t, %1; cvt.u32.u64 %0, t; }"
        : "=r"(a) : "l"(p));
    return a;
}

__device__ __forceinline__ void cp16(uint32_t dst, const void* src) {
    asm volatile("cp.async.ca.shared.global [%0], [%1], 16;"
                 :: "r"(dst), "l"(src) : "memory");
}

// hi = truncate-to-bf16(x) (bitwise), lo = rn_bf16(x - hi).
__device__ __forceinline__ void split_store4(
    float4 a, __nv_bfloat16* hi, __nv_bfloat16* lo, size_t off)
{
    uint32_t x = __float_as_uint(a.x), y = __float_as_uint(a.y);
    uint32_t z = __float_as_uint(a.z), w = __float_as_uint(a.w);
    uint32_t h01 = __byte_perm(x, y, 0x7632);
    uint32_t h23 = __byte_perm(z, w, 0x7632);
    float lx = a.x - __uint_as_float(x & 0xFFFF0000u);
    float ly = a.y - __uint_as_float(y & 0xFFFF0000u);
    float lz = a.z - __uint_as_float(z & 0xFFFF0000u);
    float lw = a.w - __uint_as_float(w & 0xFFFF0000u);
    uint32_t l01, l23;
    asm("cvt.rn.bf16x2.f32 %0, %1, %2;" : "=r"(l01) : "f"(ly), "f"(lx));
    asm("cvt.rn.bf16x2.f32 %0, %1, %2;" : "=r"(l23) : "f"(lw), "f"(lz));
    *(uint2*)(hi + off) = make_uint2(h01, h23);
    *(uint2*)(lo + off) = make_uint2(l01, l23);
}

__device__ __forceinline__ void mma_bf16(
    float d[4], uint32_t a0, uint32_t a1, uint32_t a2, uint32_t a3,
    uint32_t b0, uint32_t b1)
{
    asm volatile(
        "mma.sync.aligned.m16n8k16.row.col.f32.bf16.bf16.f32 "
        "{%0,%1,%2,%3}, {%4,%5,%6,%7}, {%8,%9}, {%0,%1,%2,%3};"
        : "+f"(d[0]), "+f"(d[1]), "+f"(d[2]), "+f"(d[3])
        : "r"(a0), "r"(a1), "r"(a2), "r"(a3), "r"(b0), "r"(b1));
}

// ===========================================================================
// Kernel 0: split X and W into bf16 hi/lo global scratch; also pad rel.
// ===========================================================================
__global__ __launch_bounds__(256) void split_prep(
    const float* __restrict__ x, const float* __restrict__ w,
    const float* __restrict__ rel)
{
    int idx = blockIdx.x * 256 + threadIdx.x;   // one float4 each
    int row = idx >> 7;
    int q   = idx & 127;
    if (row < 32768) {
        int b = row >> 6, h = row & 63;
        int n = b >> 6,  wi = b & 63;
        float4 a = *(const float4*)(x + (size_t)(wi * 64 + h) * 4096
                                      + n * 512 + q * 4);
        split_store4(a, g_xhi, g_xlo, (size_t)row * 512 + q * 4);
    } else if (row < 33792) {
        int o = row - 32768;
        float4 a = *(const float4*)(w + (size_t)o * 512 + q * 4);
        split_store4(a, g_whi, g_wlo, (size_t)o * 512 + q * 4);
    }
    // rel pad handled by dedicated tail blocks:
    int tidg = blockIdx.x * 256 + threadIdx.x - 33792 * 128;
    if (tidg >= 0 && tidg < 128 * 128) {
        int r = tidg >> 7, d = tidg & 127;
        g_relp[tidg] = (d < 127) ? rel[r * 127 + d] : 0.f;
    }
}

// ===========================================================================
// Kernel 1: QKV GEMM (exact R10 config, 282us measured).
//  D[o(128), n(256 = 4 windows x 64 h)] ; grid = (8 ot, 128 bq), 256 thr.
//  K = 512 in 16 chunks of 32, 2-stage double buffer, GPAD=40.
// ===========================================================================
#define GPAD 40   // bf16 row stride
#define KC 32
#define NCHUNK 16

// smem offsets in bf16 units
#define SW_OFF(s, hl) (((s) * 2 + (hl)) * 128 * GPAD)
#define SX_OFF(s, hl) (4 * 128 * GPAD + ((s) * 2 + (hl)) * 256 * GPAD)
#define GEMM_SMEM_BF16 (4 * 128 * GPAD + 4 * 256 * GPAD)
#define GEMM_SMEM_BYTES (GEMM_SMEM_BF16 * 2)

__global__ __launch_bounds__(256, 1) void qkv_gemm_mma(
    const float* __restrict__ gg, const float* __restrict__ gb,
    const float* __restrict__ gm, const float* __restrict__ gv)
{
    extern __shared__ __nv_bfloat16 smem[];
    const uint32_t sb = smem_u32(smem);

    const int tid  = threadIdx.x;
    const int lane = tid & 31;
    const int wid  = tid >> 5;
    const int wm   = wid >> 2;          // 0..1
    const int wn   = wid & 3;           // 0..3
    const int o0   = wm * 64;
    const int n0   = wn * 64;
    const int gid  = lane >> 2;         // 0..7
    const int tig  = lane & 3;          // 0..3
    const int ot   = blockIdx.x;
    const int bq   = blockIdx.y;        // 4-window group

    const __nv_bfloat16* whiB = g_whi + (size_t)(ot * 128) * 512;
    const __nv_bfloat16* wloB = g_wlo + (size_t)(ot * 128) * 512;
    const __nv_bfloat16* xhiB = g_xhi + (size_t)(bq * 256) * 512;
    const __nv_bfloat16* xloB = g_xlo + (size_t)(bq * 256) * 512;

    float acc[4][8][4];
#pragma unroll
    for (int m = 0; m < 4; m++)
#pragma unroll
        for (int n = 0; n < 8; n++)
#pragma unroll
            for (int r = 0; r < 4; r++) acc[m][n][r] = 0.f;

    auto load_chunk = [&](int c, int s) {
        const int ct = c * KC;
#pragma unroll
        for (int t = 0; t < 2; t++) {
            int slot = tid + t * 256;        // 0..511
            int row = slot >> 2, q = slot & 3;
            size_t g = (size_t)row * 512 + ct + q * 8;
            uint32_t d = row * GPAD + q * 8;
            cp16(sb + (SW_OFF(s, 0) + d) * 2, whiB + g);
            cp16(sb + (SW_OFF(s, 1) + d) * 2, wloB + g);
        }
#pragma unroll
        for (int t = 0; t < 4; t++) {
            int slot = tid + t * 256;        // 0..1023
            int row = slot >> 2, q = slot & 3;
            size_t g = (size_t)row * 512 + ct + q * 8;
            uint32_t d = row * GPAD + q * 8;
            cp16(sb + (SX_OFF(s, 0) + d) * 2, xhiB + g);
            cp16(sb + (SX_OFF(s, 1) + d) * 2, xloB + g);
        }
        asm volatile("cp.async.commit_group;" ::: "memory");
    };

    load_chunk(0, 0);
    load_chunk(1, 1);

    for (int c = 0; c < NCHUNK; c++) {
        const int s = c & 1;
        if (c < NCHUNK - 1) asm volatile("cp.async.wait_group 1;" ::: "memory");
        else                asm volatile("cp.async.wait_group 0;" ::: "memory");
        __syncthreads();

        const __nv_bfloat16* Whi = smem + SW_OFF(s, 0);
        const __nv_bfloat16* Wlo = smem + SW_OFF(s, 1);
        const __nv_bfloat16* Xhi = smem + SX_OFF(s, 0);
        const __nv_bfloat16* Xlo = smem + SX_OFF(s, 1);

#pragma unroll
        for (int ks = 0; ks < 2; ks++) {
            const int kb = ks * 16 + tig * 2;
#pragma unroll
            for (int nh = 0; nh < 2; nh++) {
                uint32_t Bh[4][2], Bl[4][2];
#pragma unroll
                for (int n = 0; n < 4; n++) {
                    int r = (n0 + (nh * 4 + n) * 8 + gid) * GPAD + kb;
                    Bh[n][0] = *(const uint32_t*)&Xhi[r];
                    Bh[n][1] = *(const uint32_t*)&Xhi[r + 8];
                    Bl[n][0] = *(const uint32_t*)&Xlo[r];
                    Bl[n][1] = *(const uint32_t*)&Xlo[r + 8];
                }
                uint32_t Ah[4][4], Al[4][4];
#pragma unroll
                for (int m = 0; m < 4; m++) {
                    int r0 = (o0 + m * 16 + gid) * GPAD + kb;
                    int r1 = r0 + 8 * GPAD;
                    Ah[m][0] = *(const uint32_t*)&Whi[r0];
                    Ah[m][1] = *(const uint32_t*)&Whi[r1];
                    Ah[m][2] = *(const uint32_t*)&Whi[r0 + 8];
                    Ah[m][3] = *(const uint32_t*)&Whi[r1 + 8];
                    Al[m][0] = *(const uint32_t*)&Wlo[r0];
                    Al[m][1] = *(const uint32_t*)&Wlo[r1];
                    Al[m][2] = *(const uint32_t*)&Wlo[r0 + 8];
                    Al[m][3] = *(const uint32_t*)&Wlo[r1 + 8];
                }
#pragma unroll
                for (int m = 0; m < 4; m++)
#pragma unroll
                    for (int n = 0; n < 4; n++)
                        mma_bf16(acc[m][nh * 4 + n],
                                 Ah[m][0], Ah[m][1], Ah[m][2], Ah[m][3],
                                 Bh[n][0], Bh[n][1]);
#pragma unroll
                for (int m = 0; m < 4; m++)
#pragma unroll
                    for (int n = 0; n < 4; n++)
                        mma_bf16(acc[m][nh * 4 + n],
                                 Ah[m][0], Ah[m][1], Ah[m][2], Ah[m][3],
                                 Bl[n][0], Bl[n][1]);
#pragma unroll
                for (int m = 0; m < 4; m++)
#pragma unroll
                    for (int n = 0; n < 4; n++)
                        mma_bf16(acc[m][nh * 4 + n],
                                 Al[m][0], Al[m][1], Al[m][2], Al[m][3],
                                 Bh[n][0], Bh[n][1]);
            }
        }

        if (c + 2 < NCHUNK) {
            __syncthreads();
            load_chunk(c + 2, s);
        }
    }

    // ---- epilogue: BN affine + store to g_qkv ----
#pragma unroll
    for (int m = 0; m < 4; m++) {
#pragma unroll
        for (int rr = 0; rr < 2; rr++) {
            int o = ot * 128 + o0 + m * 16 + gid + rr * 8;
            float sc = gg[o] * rsqrtf(gv[o] + 1e-5f);
            float sh = gb[o] - gm[o] * sc;
#pragma unroll
            for (int n = 0; n < 8; n++) {
                int col = n0 + n * 8 + 2 * tig;
                int b = bq * 4 + (col >> 6);
                int h = col & 63;
                float2 v;
                v.x = acc[m][n][rr * 2 + 0] * sc + sh;
                v.y = acc[m][n][rr * 2 + 1] * sc + sh;
                *(float2*)(g_qkv + (size_t)b * 65536 + (size_t)o * 64 + h) = v;
            }
        }
    }
}

// ---------------------------------------------------------------------------
// Kernel 2: attention per (b, g).  grid = (8 g, 512 b), 256 threads.
// Exact R10 compute; epilogue now stores res directly to global as STG.128
// (no smem transpose round trip, no trailing barriers).
// ---------------------------------------------------------------------------
#define SM_V (64 * 68)
#define SM_R (128 * 68)
#define ATTN_SMEM_FLOATS (128 * 68 + 128 * 128)
#define ATTN_SMEM_BYTES (ATTN_SMEM_FLOATS * 4)

__global__ __launch_bounds__(256, 2) void attn_kernel(
    const float* __restrict__ simg, const float* __restrict__ simb,
    const float* __restrict__ simm, const float* __restrict__ simv,
    const float* __restrict__ outg, const float* __restrict__ outb,
    const float* __restrict__ outm, const float* __restrict__ outv,
    float* __restrict__ out)
{
    extern __shared__ float sm[];
    float* sQ = sm;                 // rows 0..31
    float* sK = sm + 32 * 68;       // rows 32..63
    float* sS = sm;                 // OVERLAY (pre-softmax sim) after sync
    float* sV = sm + SM_V;
    float* sR = sm + SM_R;
    float* sT = sm + SM_R;          // OVERLAY: transposed softmax output in
                                    // dead rel rows 0..63 (stride 68)
    const uint32_t sb = smem_u32(sm);

    const int g   = blockIdx.x;
    const int b   = blockIdx.y;
    const int n   = b >> 6;
    const int wi  = b & 63;
    const int tid = threadIdx.x;
    const int tx  = tid & 15;
    const int ty  = tid >> 4;

    // Load rel table (padded, contiguous) via cp.async
#pragma unroll
    for (int t = 0; t < 16; t++) {
        int idx = (tid + t * 256) * 4;     // 0..16380
        cp16(sb + (SM_R + idx) * 4, g_relp + idx);
    }
    // Load q/k/v tiles from the qkv scratch via cp.async
    const float* base = g_qkv + (size_t)b * 65536 + (size_t)g * 128 * 64;
#pragma unroll
    for (int t = 0; t < 8; t++) {
        int idx = (tid + t * 256) * 4;     // element index, 0..8188
        int cc = idx >> 6;
        int h  = idx & 63;
        uint32_t dst = (cc < 64) ? (cc * 68 + h)
                                 : (SM_V + (cc - 64) * 68 + h);
        cp16(sb + dst * 4, base + idx);
    }
    asm volatile("cp.async.commit_group;" ::: "memory");
    asm volatile("cp.async.wait_group 0;" ::: "memory");
    __syncthreads();

    // --------------- sim = BN(qk) + BN(qr) + BN(kr) ---------------
    const int i0 = ty * 4;
    const int j0 = tx * 4;
    const int dq0 = i0 - j0 + 60;
    const int dk0 = j0 - i0 + 60;

    float aqk[4][4], aqr[4][4], akr[4][4];
#pragma unroll
    for (int a = 0; a < 4; a++)
#pragma unroll
        for (int c = 0; c < 4; c++) { aqk[a][c] = 0.f; aqr[a][c] = 0.f; akr[a][c] = 0.f; }

#pragma unroll 4
    for (int c = 0; c < 32; c++) {
        float4 qv4 = *(const float4*)&sQ[c * 68 + i0];
        float4 kv4 = *(const float4*)&sK[c * 68 + j0];
        float4 rq0 = *(const float4*)&sR[c * 128 + dq0];
        float4 rq1 = *(const float4*)&sR[c * 128 + dq0 + 4];
        float4 rk0 = *(const float4*)&sR[(32 + c) * 128 + dk0];
        float4 rk1 = *(const float4*)&sR[(32 + c) * 128 + dk0 + 4];
        float qv[4] = {qv4.x, qv4.y, qv4.z, qv4.w};
        float kv[4] = {kv4.x, kv4.y, kv4.z, kv4.w};
        float rq[8] = {rq0.x, rq0.y, rq0.z, rq0.w, rq1.x, rq1.y, rq1.z, rq1.w};
        float rk[8] = {rk0.x, rk0.y, rk0.z, rk0.w, rk1.x, rk1.y, rk1.z, rk1.w};
#pragma unroll
        for (int ii = 0; ii < 4; ii++)
#pragma unroll
            for (int jj = 0; jj < 4; jj++) {
                aqk[ii][jj] = fmaf(qv[ii], kv[jj], aqk[ii][jj]);
                aqr[ii][jj] = fmaf(qv[ii], rq[ii - jj + 3], aqr[ii][jj]);
                akr[ii][jj] = fmaf(kv[jj], rk[jj - ii + 3], akr[ii][jj]);
            }
    }

    const float s_qk = simg[g]      * rsqrtf(simv[g]      + 1e-5f);
    const float s_qr = simg[8 + g]  * rsqrtf(simv[8 + g]  + 1e-5f);
    const float s_kr = simg[16 + g] * rsqrtf(simv[16 + g] + 1e-5f);
    const float sh_sum = (simb[g]      - simm[g]      * s_qk)
                       + (simb[8 + g]  - simm[8 + g]  * s_qr)
                       + (simb[16 + g] - simm[16 + g] * s_kr);

    __syncthreads();   // all reads of q/k (and rel rows 0..63) done
#pragma unroll
    for (int ii = 0; ii < 4; ii++)
#pragma unroll
        for (int jj = 0; jj < 4; jj++)
            sS[(i0 + ii) * 68 + j0 + jj] =
                s_qk * aqk[ii][jj] + s_qr * aqr[ii][jj] + s_kr * akr[ii][jj] + sh_sum;
    __syncthreads();

    // ---- softmax over j; output written transposed into sT[j][i] ----
    {
        int warp = tid >> 5, lane = tid & 31;
#pragma unroll
        for (int r = 0; r < 8; r++) {
            int i = warp * 8 + r;
            float a0 = sS[i * 68 + lane];
            float a1 = sS[i * 68 + lane + 32];
            float mx = fmaxf(a0, a1);
#pragma unroll
            for (int off = 16; off > 0; off >>= 1)
                mx = fmaxf(mx, __shfl_xor_sync(0xffffffffu, mx, off));
            float e0 = __expf(a0 - mx);
            float e1 = __expf(a1 - mx);
            float s = e0 + e1;
#pragma unroll
            for (int off = 16; off > 0; off >>= 1)
                s += __shfl_xor_sync(0xffffffffu, s, off);
            float inv = 1.0f / s;
            sT[lane * 68 + i]        = e0 * inv;   // sim[i][lane]
            sT[(lane + 32) * 68 + i] = e1 * inv;   // sim[i][lane+32]
        }
    }
    __syncthreads();

    // --------------- sv / sve (transposed sim reads, conflict-free) -------
    const int c0  = ty * 4;
    const int ii0 = tx * 4;
    float asv[4][4], asve[4][4];
#pragma unroll
    for (int a = 0; a < 4; a++)
#pragma unroll
        for (int c = 0; c < 4; c++) { asv[a][c] = 0.f; asve[a][c] = 0.f; }

    // carry: rcar[cc] holds rel[(64+c0+cc)*128 + ii0 - 4*jq + 64 .. +67]
    float4 rcar[4];
#pragma unroll
    for (int cc = 0; cc < 4; cc++)
        rcar[cc] = *(const float4*)&sR[(64 + c0 + cc) * 128 + ii0 + 64];

#pragma unroll 2
    for (int jq = 0; jq < 16; jq++) {
        // sjf[jj][t] = sim[ii0+t][4*jq+jj]  (float4 over i from sT)
        float sjf[4][4];
#pragma unroll
        for (int jj = 0; jj < 4; jj++) {
            float4 v = *(const float4*)&sT[(jq * 4 + jj) * 68 + ii0];
            sjf[jj][0] = v.x; sjf[jj][1] = v.y; sjf[jj][2] = v.z; sjf[jj][3] = v.w;
        }
        float4 vv[4];
#pragma unroll
        for (int t = 0; t < 4; t++) vv[t] = *(const float4*)&sV[(c0 + t) * 68 + jq * 4];

#pragma unroll
        for (int cc = 0; cc < 4; cc++) {
            float4 r0 = *(const float4*)&sR[(64 + c0 + cc) * 128 + ii0 - jq * 4 + 60];
            float rv8[8] = {r0.x, r0.y, r0.z, r0.w,
                            rcar[cc].x, rcar[cc].y, rcar[cc].z, rcar[cc].w};
#pragma unroll
            for (int t = 0; t < 4; t++) {
                float a = asv[cc][t];
                a = fmaf(sjf[0][t], vv[cc].x, a);
                a = fmaf(sjf[1][t], vv[cc].y, a);
                a = fmaf(sjf[2][t], vv[cc].z, a);
                a = fmaf(sjf[3][t], vv[cc].w, a);
                asv[cc][t] = a;
                float e = asve[cc][t];
                e = fmaf(sjf[0][t], rv8[t + 3], e);
                e = fmaf(sjf[1][t], rv8[t + 2], e);
                e = fmaf(sjf[2][t], rv8[t + 1], e);
                e = fmaf(sjf[3][t], rv8[t + 0], e);
                asve[cc][t] = e;
            }
            rcar[cc] = r0;
        }
    }

    // --------------- out BN + interleaved sum, DIRECT global stores -------
    // out[(wi*64 + i)*4096 + n*512 + g*64 + c], c = c0..c0+3 contiguous
    // -> one STG.128 per (thread, t).  16B-aligned since c0 = 4*ty.
    float* ob = out + (size_t)(wi * 64) * 4096 + n * 512 + g * 64;
    float sc[4], sh[4];
#pragma unroll
    for (int cc = 0; cc < 4; cc++) {
        int c  = c0 + cc;
        int o0 = g * 128 + 2 * c;
        float sc0 = outg[o0]     * rsqrtf(outv[o0]     + 1e-5f);
        float sh0 = outb[o0]     - outm[o0]     * sc0;
        float sc1 = outg[o0 + 1] * rsqrtf(outv[o0 + 1] + 1e-5f);
        float sh1 = outb[o0 + 1] - outm[o0 + 1] * sc1;
        sc[cc] = sc0;           // applied to asv
        sh[cc] = sh0 + sh1;     // combined shift
        // fold sc1 into asve now:
#pragma unroll
        for (int t = 0; t < 4; t++)
            asve[cc][t] *= sc1;
    }
#pragma unroll
    for (int t = 0; t < 4; t++) {
        float4 v;
        v.x = sc[0] * asv[0][t] + asve[0][t] + sh[0];
        v.y = sc[1] * asv[1][t] + asve[1][t] + sh[1];
        v.z = sc[2] * asv[2][t] + asve[2][t] + sh[2];
        v.w = sc[3] * asv[3][t] + asve[3][t] + sh[3];
        *(float4*)(ob + (size_t)(ii0 + t) * 4096 + c0) = v;
    }
}

// ---------------------------------------------------------------------------
extern "C" void kernel_launch(void* const* d_in, const int* in_sizes, int n_in,
                              void* d_out, int out_size)
{
    const float* x     = (const float*)d_in[0];
    const float* qkv_w = (const float*)d_in[1];
    const float* rel   = (const float*)d_in[2];
    const float* qkv_g = (const float*)d_in[3];
    const float* qkv_b = (const float*)d_in[4];
    const float* qkv_m = (const float*)d_in[5];
    const float* qkv_v = (const float*)d_in[6];
    const float* sim_g = (const float*)d_in[7];
    const float* sim_b = (const float*)d_in[8];
    const float* sim_m = (const float*)d_in[9];
    const float* sim_v = (const float*)d_in[10];
    const float* out_g = (const float*)d_in[11];
    const float* out_b = (const float*)d_in[12];
    const float* out_m = (const float*)d_in[13];
    const float* out_v = (const float*)d_in[14];
    float* out = (float*)d_out;

    // 33792*128 float4 slots for X/W split + 16384 threads for rel pad
    int total_threads = 33792 * 128 + 128 * 128;
    split_prep<<<(total_threads + 255) / 256, 256>>>(x, qkv_w, rel);

    cudaFuncSetAttribute(qkv_gemm_mma,
                         cudaFuncAttributeMaxDynamicSharedMemorySize,
                         GEMM_SMEM_BYTES);
    qkv_gemm_mma<<<dim3(8, 128), 256, GEMM_SMEM_BYTES>>>(
        qkv_g, qkv_b, qkv_m, qkv_v);

    cudaFuncSetAttribute(attn_kernel,
                         cudaFuncAttributeMaxDynamicSharedMemorySize,
                         ATTN_SMEM_BYTES);
    attn_kernel<<<dim3(8, 512), 256, ATTN_SMEM_BYTES>>>(
        sim_g, sim_b, sim_m, sim_v,
        out_g, out_b, out_m, out_v, out);
}

// round 16
// speedup vs baseline: 1.0895x; 1.0077x over previous
#include <cuda_runtime.h>
#include <cuda_bf16.h>
#include <cstdint>

// Problem constants
#define L_DIM 4096
#define N_DIM 8
#define C_DIM 512
#define OUT_DIM 512
#define G_DIM 8
#define KS_DIM 64
#define W_DIM 64          // L / KS
#define B_DIM 512         // N * W

// Scratch: qkv intermediate [B][1024][64] (BN already applied)
__device__ float g_qkv[(size_t)B_DIM * 1024 * 64];
// Split bf16 copies (X relaid to [b*64+h][c], W as [o][c])
__device__ __nv_bfloat16 g_xhi[(size_t)32768 * 512];
__device__ __nv_bfloat16 g_xlo[(size_t)32768 * 512];
__device__ __nv_bfloat16 g_whi[(size_t)1024 * 512];
__device__ __nv_bfloat16 g_wlo[(size_t)1024 * 512];
// Padded relative table: row stride 128 (float4-aligned rows)
__device__ float g_relp[128 * 128];

// ===========================================================================
// helpers
// ===========================================================================
__device__ __forceinline__ uint32_t smem_u32(const void* p) {
    uint32_t a;
    asm("{ .reg .u64 t; cvta.to.shared.u64 t, %1; cvt.u32.u64 %0, t; }"
        : "=r"(a) : "l"(p));
    return a;
}

__device__ __forceinline__ void cp16(uint32_t dst, const void* src) {
    asm volatile("cp.async.ca.shared.global [%0], [%1], 16;"
                 :: "r"(dst), "l"(src) : "memory");
}

// hi = truncate-to-bf16(x) (bitwise), lo = rn_bf16(x - hi).
__device__ __forceinline__ void split_store4(
    float4 a, __nv_bfloat16* hi, __nv_bfloat16* lo, size_t off)
{
    uint32_t x = __float_as_uint(a.x), y = __float_as_uint(a.y);
    uint32_t z = __float_as_uint(a.z), w = __float_as_uint(a.w);
    uint32_t h01 = __byte_perm(x, y, 0x7632);
    uint32_t h23 = __byte_perm(z, w, 0x7632);
    float lx = a.x - __uint_as_float(x & 0xFFFF0000u);
    float ly = a.y - __uint_as_float(y & 0xFFFF0000u);
    float lz = a.z - __uint_as_float(z & 0xFFFF0000u);
    float lw = a.w - __uint_as_float(w & 0xFFFF0000u);
    uint32_t l01, l23;
    asm("cvt.rn.bf16x2.f32 %0, %1, %2;" : "=r"(l01) : "f"(ly), "f"(lx));
    asm("cvt.rn.bf16x2.f32 %0, %1, %2;" : "=r"(l23) : "f"(lw), "f"(lz));
    *(uint2*)(hi + off) = make_uint2(h01, h23);
    *(uint2*)(lo + off) = make_uint2(l01, l23);
}

__device__ __forceinline__ void mma_bf16(
    float d[4], uint32_t a0, uint32_t a1, uint32_t a2, uint32_t a3,
    uint32_t b0, uint32_t b1)
{
    asm volatile(
        "mma.sync.aligned.m16n8k16.row.col.f32.bf16.bf16.f32 "
        "{%0,%1,%2,%3}, {%4,%5,%6,%7}, {%8,%9}, {%0,%1,%2,%3};"
        : "+f"(d[0]), "+f"(d[1]), "+f"(d[2]), "+f"(d[3])
        : "r"(a0), "r"(a1), "r"(a2), "r"(a3), "r"(b0), "r"(b1));
}

// ===========================================================================
// Kernel 0: split X and W into bf16 hi/lo global scratch; also pad rel.
// ===========================================================================
__global__ __launch_bounds__(256) void split_prep(
    const float* __restrict__ x, const float* __restrict__ w,
    const float* __restrict__ rel)
{
    int idx = blockIdx.x * 256 + threadIdx.x;   // one float4 each
    int row = idx >> 7;
    int q   = idx & 127;
    if (row < 32768) {
        int b = row >> 6, h = row & 63;
        int n = b >> 6,  wi = b & 63;
        float4 a = *(const float4*)(x + (size_t)(wi * 64 + h) * 4096
                                      + n * 512 + q * 4);
        split_store4(a, g_xhi, g_xlo, (size_t)row * 512 + q * 4);
    } else if (row < 33792) {
        int o = row - 32768;
        float4 a = *(const float4*)(w + (size_t)o * 512 + q * 4);
        split_store4(a, g_whi, g_wlo, (size_t)o * 512 + q * 4);
    }
    // rel pad handled by dedicated tail blocks:
    int tidg = blockIdx.x * 256 + threadIdx.x - 33792 * 128;
    if (tidg >= 0 && tidg < 128 * 128) {
        int r = tidg >> 7, d = tidg & 127;
        g_relp[tidg] = (d < 127) ? rel[r * 127 + d] : 0.f;
    }
}

// ===========================================================================
// Kernel 1: QKV GEMM (exact R10 config, 282us measured).
//  D[o(128), n(256 = 4 windows x 64 h)] ; grid = (8 ot, 128 bq), 256 thr.
//  K = 512 in 16 chunks of 32, 2-stage double buffer, GPAD=40.
// ===========================================================================
#define GPAD 40   // bf16 row stride
#define KC 32
#define NCHUNK 16

// smem offsets in bf16 units
#define SW_OFF(s, hl) (((s) * 2 + (hl)) * 128 * GPAD)
#define SX_OFF(s, hl) (4 * 128 * GPAD + ((s) * 2 + (hl)) * 256 * GPAD)
#define GEMM_SMEM_BF16 (4 * 128 * GPAD + 4 * 256 * GPAD)
#define GEMM_SMEM_BYTES (GEMM_SMEM_BF16 * 2)

__global__ __launch_bounds__(256, 1) void qkv_gemm_mma(
    const float* __restrict__ gg, const float* __restrict__ gb,
    const float* __restrict__ gm, const float* __restrict__ gv)
{
    extern __shared__ __nv_bfloat16 smem[];
    const uint32_t sb = smem_u32(smem);

    const int tid  = threadIdx.x;
    const int lane = tid & 31;
    const int wid  = tid >> 5;
    const int wm   = wid >> 2;          // 0..1
    const int wn   = wid & 3;           // 0..3
    const int o0   = wm * 64;
    const int n0   = wn * 64;
    const int gid  = lane >> 2;         // 0..7
    const int tig  = lane & 3;          // 0..3
    const int ot   = blockIdx.x;
    const int bq   = blockIdx.y;        // 4-window group

    const __nv_bfloat16* whiB = g_whi + (size_t)(ot * 128) * 512;
    const __nv_bfloat16* wloB = g_wlo + (size_t)(ot * 128) * 512;
    const __nv_bfloat16* xhiB = g_xhi + (size_t)(bq * 256) * 512;
    const __nv_bfloat16* xloB = g_xlo + (size_t)(bq * 256) * 512;

    float acc[4][8][4];
#pragma unroll
    for (int m = 0; m < 4; m++)
#pragma unroll
        for (int n = 0; n < 8; n++)
#pragma unroll
            for (int r = 0; r < 4; r++) acc[m][n][r] = 0.f;

    auto load_chunk = [&](int c, int s) {
        const int ct = c * KC;
#pragma unroll
        for (int t = 0; t < 2; t++) {
            int slot = tid + t * 256;        // 0..511
            int row = slot >> 2, q = slot & 3;
            size_t g = (size_t)row * 512 + ct + q * 8;
            uint32_t d = row * GPAD + q * 8;
            cp16(sb + (SW_OFF(s, 0) + d) * 2, whiB + g);
            cp16(sb + (SW_OFF(s, 1) + d) * 2, wloB + g);
        }
#pragma unroll
        for (int t = 0; t < 4; t++) {
            int slot = tid + t * 256;        // 0..1023
            int row = slot >> 2, q = slot & 3;
            size_t g = (size_t)row * 512 + ct + q * 8;
            uint32_t d = row * GPAD + q * 8;
            cp16(sb + (SX_OFF(s, 0) + d) * 2, xhiB + g);
            cp16(sb + (SX_OFF(s, 1) + d) * 2, xloB + g);
        }
        asm volatile("cp.async.commit_group;" ::: "memory");
    };

    load_chunk(0, 0);
    load_chunk(1, 1);

    for (int c = 0; c < NCHUNK; c++) {
        const int s = c & 1;
        if (c < NCHUNK - 1) asm volatile("cp.async.wait_group 1;" ::: "memory");
        else                asm volatile("cp.async.wait_group 0;" ::: "memory");
        __syncthreads();

        const __nv_bfloat16* Whi = smem + SW_OFF(s, 0);
        const __nv_bfloat16* Wlo = smem + SW_OFF(s, 1);
        const __nv_bfloat16* Xhi = smem + SX_OFF(s, 0);
        const __nv_bfloat16* Xlo = smem + SX_OFF(s, 1);

#pragma unroll
        for (int ks = 0; ks < 2; ks++) {
            const int kb = ks * 16 + tig * 2;
#pragma unroll
            for (int nh = 0; nh < 2; nh++) {
                uint32_t Bh[4][2], Bl[4][2];
#pragma unroll
                for (int n = 0; n < 4; n++) {
                    int r = (n0 + (nh * 4 + n) * 8 + gid) * GPAD + kb;
                    Bh[n][0] = *(const uint32_t*)&Xhi[r];
                    Bh[n][1] = *(const uint32_t*)&Xhi[r + 8];
                    Bl[n][0] = *(const uint32_t*)&Xlo[r];
                    Bl[n][1] = *(const uint32_t*)&Xlo[r + 8];
                }
                uint32_t Ah[4][4], Al[4][4];
#pragma unroll
                for (int m = 0; m < 4; m++) {
                    int r0 = (o0 + m * 16 + gid) * GPAD + kb;
                    int r1 = r0 + 8 * GPAD;
                    Ah[m][0] = *(const uint32_t*)&Whi[r0];
                    Ah[m][1] = *(const uint32_t*)&Whi[r1];
                    Ah[m][2] = *(const uint32_t*)&Whi[r0 + 8];
                    Ah[m][3] = *(const uint32_t*)&Whi[r1 + 8];
                    Al[m][0] = *(const uint32_t*)&Wlo[r0];
                    Al[m][1] = *(const uint32_t*)&Wlo[r1];
                    Al[m][2] = *(const uint32_t*)&Wlo[r0 + 8];
                    Al[m][3] = *(const uint32_t*)&Wlo[r1 + 8];
                }
#pragma unroll
                for (int m = 0; m < 4; m++)
#pragma unroll
                    for (int n = 0; n < 4; n++)
                        mma_bf16(acc[m][nh * 4 + n],
                                 Ah[m][0], Ah[m][1], Ah[m][2], Ah[m][3],
                                 Bh[n][0], Bh[n][1]);
#pragma unroll
                for (int m = 0; m < 4; m++)
#pragma unroll
                    for (int n = 0; n < 4; n++)
                        mma_bf16(acc[m][nh * 4 + n],
                                 Ah[m][0], Ah[m][1], Ah[m][2], Ah[m][3],
                                 Bl[n][0], Bl[n][1]);
#pragma unroll
                for (int m = 0; m < 4; m++)
#pragma unroll
                    for (int n = 0; n < 4; n++)
                        mma_bf16(acc[m][nh * 4 + n],
                                 Al[m][0], Al[m][1], Al[m][2], Al[m][3],
                                 Bh[n][0], Bh[n][1]);
            }
        }

        if (c + 2 < NCHUNK) {
            __syncthreads();
            load_chunk(c + 2, s);
        }
    }

    // ---- epilogue: BN affine + store to g_qkv ----
#pragma unroll
    for (int m = 0; m < 4; m++) {
#pragma unroll
        for (int rr = 0; rr < 2; rr++) {
            int o = ot * 128 + o0 + m * 16 + gid + rr * 8;
            float sc = gg[o] * rsqrtf(gv[o] + 1e-5f);
            float sh = gb[o] - gm[o] * sc;
#pragma unroll
            for (int n = 0; n < 8; n++) {
                int col = n0 + n * 8 + 2 * tig;
                int b = bq * 4 + (col >> 6);
                int h = col & 63;
                float2 v;
                v.x = acc[m][n][rr * 2 + 0] * sc + sh;
                v.y = acc[m][n][rr * 2 + 1] * sc + sh;
                *(float2*)(g_qkv + (size_t)b * 65536 + (size_t)o * 64 + h) = v;
            }
        }
    }
}

// ---------------------------------------------------------------------------
// Kernel 2: attention per (b, g).  grid = (8 g, 512 b), 256 threads.
// R15 compute; softmax transpose now buffered in registers and emitted as
// 4 conflict-free STS.128 per lane (lane l owns transposed rows l and l+32).
// ---------------------------------------------------------------------------
#define SM_V (64 * 68)
#define SM_R (128 * 68)
#define ATTN_SMEM_FLOATS (128 * 68 + 128 * 128)
#define ATTN_SMEM_BYTES (ATTN_SMEM_FLOATS * 4)

__global__ __launch_bounds__(256, 2) void attn_kernel(
    const float* __restrict__ simg, const float* __restrict__ simb,
    const float* __restrict__ simm, const float* __restrict__ simv,
    const float* __restrict__ outg, const float* __restrict__ outb,
    const float* __restrict__ outm, const float* __restrict__ outv,
    float* __restrict__ out)
{
    extern __shared__ float sm[];
    float* sQ = sm;                 // rows 0..31
    float* sK = sm + 32 * 68;       // rows 32..63
    float* sS = sm;                 // OVERLAY (pre-softmax sim) after sync
    float* sV = sm + SM_V;
    float* sR = sm + SM_R;
    float* sT = sm + SM_R;          // OVERLAY: transposed softmax output in
                                    // dead rel rows 0..63 (stride 68)
    const uint32_t sb = smem_u32(sm);

    const int g   = blockIdx.x;
    const int b   = blockIdx.y;
    const int n   = b >> 6;
    const int wi  = b & 63;
    const int tid = threadIdx.x;
    const int tx  = tid & 15;
    const int ty  = tid >> 4;

    // Load rel table (padded, contiguous) via cp.async
#pragma unroll
    for (int t = 0; t < 16; t++) {
        int idx = (tid + t * 256) * 4;     // 0..16380
        cp16(sb + (SM_R + idx) * 4, g_relp + idx);
    }
    // Load q/k/v tiles from the qkv scratch via cp.async
    const float* base = g_qkv + (size_t)b * 65536 + (size_t)g * 128 * 64;
#pragma unroll
    for (int t = 0; t < 8; t++) {
        int idx = (tid + t * 256) * 4;     // element index, 0..8188
        int cc = idx >> 6;
        int h  = idx & 63;
        uint32_t dst = (cc < 64) ? (cc * 68 + h)
                                 : (SM_V + (cc - 64) * 68 + h);
        cp16(sb + dst * 4, base + idx);
    }
    asm volatile("cp.async.commit_group;" ::: "memory");
    asm volatile("cp.async.wait_group 0;" ::: "memory");
    __syncthreads();

    // --------------- sim = BN(qk) + BN(qr) + BN(kr) ---------------
    const int i0 = ty * 4;
    const int j0 = tx * 4;
    const int dq0 = i0 - j0 + 60;
    const int dk0 = j0 - i0 + 60;

    float aqk[4][4], aqr[4][4], akr[4][4];
#pragma unroll
    for (int a = 0; a < 4; a++)
#pragma unroll
        for (int c = 0; c < 4; c++) { aqk[a][c] = 0.f; aqr[a][c] = 0.f; akr[a][c] = 0.f; }

#pragma unroll 4
    for (int c = 0; c < 32; c++) {
        float4 qv4 = *(const float4*)&sQ[c * 68 + i0];
        float4 kv4 = *(const float4*)&sK[c * 68 + j0];
        float4 rq0 = *(const float4*)&sR[c * 128 + dq0];
        float4 rq1 = *(const float4*)&sR[c * 128 + dq0 + 4];
        float4 rk0 = *(const float4*)&sR[(32 + c) * 128 + dk0];
        float4 rk1 = *(const float4*)&sR[(32 + c) * 128 + dk0 + 4];
        float qv[4] = {qv4.x, qv4.y, qv4.z, qv4.w};
        float kv[4] = {kv4.x, kv4.y, kv4.z, kv4.w};
        float rq[8] = {rq0.x, rq0.y, rq0.z, rq0.w, rq1.x, rq1.y, rq1.z, rq1.w};
        float rk[8] = {rk0.x, rk0.y, rk0.z, rk0.w, rk1.x, rk1.y, rk1.z, rk1.w};
#pragma unroll
        for (int ii = 0; ii < 4; ii++)
#pragma unroll
            for (int jj = 0; jj < 4; jj++) {
                aqk[ii][jj] = fmaf(qv[ii], kv[jj], aqk[ii][jj]);
                aqr[ii][jj] = fmaf(qv[ii], rq[ii - jj + 3], aqr[ii][jj]);
                akr[ii][jj] = fmaf(kv[jj], rk[jj - ii + 3], akr[ii][jj]);
            }
    }

    const float s_qk = simg[g]      * rsqrtf(simv[g]      + 1e-5f);
    const float s_qr = simg[8 + g]  * rsqrtf(simv[8 + g]  + 1e-5f);
    const float s_kr = simg[16 + g] * rsqrtf(simv[16 + g] + 1e-5f);
    const float sh_sum = (simb[g]      - simm[g]      * s_qk)
                       + (simb[8 + g]  - simm[8 + g]  * s_qr)
                       + (simb[16 + g] - simm[16 + g] * s_kr);

    __syncthreads();   // all reads of q/k (and rel rows 0..63) done
#pragma unroll
    for (int ii = 0; ii < 4; ii++)
#pragma unroll
        for (int jj = 0; jj < 4; jj++)
            sS[(i0 + ii) * 68 + j0 + jj] =
                s_qk * aqk[ii][jj] + s_qr * aqr[ii][jj] + s_kr * akr[ii][jj] + sh_sum;
    __syncthreads();

    // ---- softmax over j; transposed rows buffered in regs, then 4x STS.128
    {
        int warp = tid >> 5, lane = tid & 31;
        float pe0[8], pe1[8];
#pragma unroll
        for (int r = 0; r < 8; r++) {
            int i = warp * 8 + r;
            float a0 = sS[i * 68 + lane];
            float a1 = sS[i * 68 + lane + 32];
            float mx = fmaxf(a0, a1);
#pragma unroll
            for (int off = 16; off > 0; off >>= 1)
                mx = fmaxf(mx, __shfl_xor_sync(0xffffffffu, mx, off));
            float e0 = __expf(a0 - mx);
            float e1 = __expf(a1 - mx);
            float s = e0 + e1;
#pragma unroll
            for (int off = 16; off > 0; off >>= 1)
                s += __shfl_xor_sync(0xffffffffu, s, off);
            float inv = 1.0f / s;
            pe0[r] = e0 * inv;    // sim[i][lane]
            pe1[r] = e1 * inv;    // sim[i][lane+32]
        }
        int iw = warp * 8;
        *(float4*)&sT[lane * 68 + iw] =
            make_float4(pe0[0], pe0[1], pe0[2], pe0[3]);
        *(float4*)&sT[lane * 68 + iw + 4] =
            make_float4(pe0[4], pe0[5], pe0[6], pe0[7]);
        *(float4*)&sT[(lane + 32) * 68 + iw] =
            make_float4(pe1[0], pe1[1], pe1[2], pe1[3]);
        *(float4*)&sT[(lane + 32) * 68 + iw + 4] =
            make_float4(pe1[4], pe1[5], pe1[6], pe1[7]);
    }
    __syncthreads();

    // --------------- sv / sve (transposed sim reads, conflict-free) -------
    const int c0  = ty * 4;
    const int ii0 = tx * 4;
    float asv[4][4], asve[4][4];
#pragma unroll
    for (int a = 0; a < 4; a++)
#pragma unroll
        for (int c = 0; c < 4; c++) { asv[a][c] = 0.f; asve[a][c] = 0.f; }

    // carry: rcar[cc] holds rel[(64+c0+cc)*128 + ii0 - 4*jq + 64 .. +67]
    float4 rcar[4];
#pragma unroll
    for (int cc = 0; cc < 4; cc++)
        rcar[cc] = *(const float4*)&sR[(64 + c0 + cc) * 128 + ii0 + 64];

#pragma unroll 2
    for (int jq = 0; jq < 16; jq++) {
        // sjf[jj][t] = sim[ii0+t][4*jq+jj]  (float4 over i from sT)
        float sjf[4][4];
#pragma unroll
        for (int jj = 0; jj < 4; jj++) {
            float4 v = *(const float4*)&sT[(jq * 4 + jj) * 68 + ii0];
            sjf[jj][0] = v.x; sjf[jj][1] = v.y; sjf[jj][2] = v.z; sjf[jj][3] = v.w;
        }
        float4 vv[4];
#pragma unroll
        for (int t = 0; t < 4; t++) vv[t] = *(const float4*)&sV[(c0 + t) * 68 + jq * 4];

#pragma unroll
        for (int cc = 0; cc < 4; cc++) {
            float4 r0 = *(const float4*)&sR[(64 + c0 + cc) * 128 + ii0 - jq * 4 + 60];
            float rv8[8] = {r0.x, r0.y, r0.z, r0.w,
                            rcar[cc].x, rcar[cc].y, rcar[cc].z, rcar[cc].w};
#pragma unroll
            for (int t = 0; t < 4; t++) {
                float a = asv[cc][t];
                a = fmaf(sjf[0][t], vv[cc].x, a);
                a = fmaf(sjf[1][t], vv[cc].y, a);
                a = fmaf(sjf[2][t], vv[cc].z, a);
                a = fmaf(sjf[3][t], vv[cc].w, a);
                asv[cc][t] = a;
                float e = asve[cc][t];
                e = fmaf(sjf[0][t], rv8[t + 3], e);
                e = fmaf(sjf[1][t], rv8[t + 2], e);
                e = fmaf(sjf[2][t], rv8[t + 1], e);
                e = fmaf(sjf[3][t], rv8[t + 0], e);
                asve[cc][t] = e;
            }
            rcar[cc] = r0;
        }
    }

    // --------------- out BN + interleaved sum, DIRECT global stores -------
    float* ob = out + (size_t)(wi * 64) * 4096 + n * 512 + g * 64;
    float sc[4], sh[4];
#pragma unroll
    for (int cc = 0; cc < 4; cc++) {
        int c  = c0 + cc;
        int o0 = g * 128 + 2 * c;
        float sc0 = outg[o0]     * rsqrtf(outv[o0]     + 1e-5f);
        float sh0 = outb[o0]     - outm[o0]     * sc0;
        float sc1 = outg[o0 + 1] * rsqrtf(outv[o0 + 1] + 1e-5f);
        float sh1 = outb[o0 + 1] - outm[o0 + 1] * sc1;
        sc[cc] = sc0;
        sh[cc] = sh0 + sh1;
#pragma unroll
        for (int t = 0; t < 4; t++)
            asve[cc][t] *= sc1;
    }
#pragma unroll
    for (int t = 0; t < 4; t++) {
        float4 v;
        v.x = sc[0] * asv[0][t] + asve[0][t] + sh[0];
        v.y = sc[1] * asv[1][t] + asve[1][t] + sh[1];
        v.z = sc[2] * asv[2][t] + asve[2][t] + sh[2];
        v.w = sc[3] * asv[3][t] + asve[3][t] + sh[3];
        *(float4*)(ob + (size_t)(ii0 + t) * 4096 + c0) = v;
    }
}

// ---------------------------------------------------------------------------
extern "C" void kernel_launch(void* const* d_in, const int* in_sizes, int n_in,
                              void* d_out, int out_size)
{
    const float* x     = (const float*)d_in[0];
    const float* qkv_w = (const float*)d_in[1];
    const float* rel   = (const float*)d_in[2];
    const float* qkv_g = (const float*)d_in[3];
    const float* qkv_b = (const float*)d_in[4];
    const float* qkv_m = (const float*)d_in[5];
    const float* qkv_v = (const float*)d_in[6];
    const float* sim_g = (const float*)d_in[7];
    const float* sim_b = (const float*)d_in[8];
    const float* sim_m = (const float*)d_in[9];
    const float* sim_v = (const float*)d_in[10];
    const float* out_g = (const float*)d_in[11];
    const float* out_b = (const float*)d_in[12];
    const float* out_m = (const float*)d_in[13];
    const float* out_v = (const float*)d_in[14];
    float* out = (float*)d_out;

    // 33792*128 float4 slots for X/W split + 16384 threads for rel pad
    int total_threads = 33792 * 128 + 128 * 128;
    split_prep<<<(total_threads + 255) / 256, 256>>>(x, qkv_w, rel);

    cudaFuncSetAttribute(qkv_gemm_mma,
                         cudaFuncAttributeMaxDynamicSharedMemorySize,
                         GEMM_SMEM_BYTES);
    qkv_gemm_mma<<<dim3(8, 128), 256, GEMM_SMEM_BYTES>>>(
        qkv_g, qkv_b, qkv_m, qkv_v);

    cudaFuncSetAttribute(attn_kernel,
                         cudaFuncAttributeMaxDynamicSharedMemorySize,
                         ATTN_SMEM_BYTES);
    attn_kernel<<<dim3(8, 512), 256, ATTN_SMEM_BYTES>>>(
        sim_g, sim_b, sim_m, sim_v,
        out_g, out_b, out_m, out_v, out);
}